// round 1
// baseline (speedup 1.0000x reference)
#include <cuda_runtime.h>
#include <cuda_bf16.h>
#include <math.h>

// ---------------- scratch (static device globals; no allocation) ----------------
#define NTOK 4096
#define DMODEL 320
#define FFI 1280
#define HEADS 8
#define DH 40
#define CTXN 77
#define CTXD 768

__device__ float g_s[DMODEL];               // folded GN scale per channel
__device__ float g_t[DMODEL];               // folded GN bias per channel
__device__ float g_Wp[DMODEL * DMODEL];     // folded pin weight
__device__ float g_bp[DMODEL];              // folded pin bias
__device__ float g_h[NTOK * DMODEL];        // residual stream [n, c]
__device__ float g_ln[NTOK * DMODEL];       // layernorm output
__device__ float g_qb[NTOK * DMODEL];
__device__ float g_kb[NTOK * DMODEL];
__device__ float g_vb[NTOK * DMODEL];
__device__ float g_ao[NTOK * DMODEL];       // attention out
__device__ float g_ff[NTOK * 2 * FFI];      // ff1 out [n, 2560]
__device__ float g_fa[NTOK * FFI];          // geglu out [n, 1280]

// ---------------- GroupNorm stats -> per-channel scale/bias ----------------
// 32 groups x 10 channels x 4096 spatial. Channels contiguous per group.
__global__ void gn_stats_kernel(const float* __restrict__ x,
                                const float* __restrict__ gn_w,
                                const float* __restrict__ gn_b) {
    int g = blockIdx.x;
    int tid = threadIdx.x;
    const float* base = x + (size_t)g * 10 * 4096;
    float s = 0.f, ss = 0.f;
    for (int i = tid; i < 40960; i += 256) {
        float v = base[i];
        s += v; ss += v * v;
    }
    __shared__ float r1[256], r2[256];
    r1[tid] = s; r2[tid] = ss;
    __syncthreads();
    for (int off = 128; off > 0; off >>= 1) {
        if (tid < off) { r1[tid] += r1[tid + off]; r2[tid] += r2[tid + off]; }
        __syncthreads();
    }
    if (tid < 10) {
        float mu = r1[0] / 40960.f;
        float var = r2[0] / 40960.f - mu * mu;
        float inv = rsqrtf(var + 1e-6f);
        int c = g * 10 + tid;
        float w = gn_w[c];
        g_s[c] = inv * w;
        g_t[c] = gn_b[c] - mu * inv * w;
    }
}

// Fold GN affine into pin conv weight: Wp[o,c] = pin_w[o,c]*s[c]; bp[o] = pin_b[o] + sum_c pin_w[o,c]*t[c]
__global__ void fold_pin_kernel(const float* __restrict__ pin_w,
                                const float* __restrict__ pin_b) {
    int o = blockIdx.x;
    int tid = threadIdx.x;  // 64
    float acc = 0.f;
    for (int c = tid; c < DMODEL; c += 64) {
        float w = pin_w[o * DMODEL + c];
        g_Wp[o * DMODEL + c] = w * g_s[c];
        acc += w * g_t[c];
    }
    __shared__ float r[64];
    r[tid] = acc;
    __syncthreads();
    for (int off = 32; off > 0; off >>= 1) {
        if (tid < off) r[tid] += r[tid + off];
        __syncthreads();
    }
    if (tid == 0) g_bp[o] = pin_b[o] + r[0];
}

// ---------------- generic strided SGEMM ----------------
// C[m,n] = sum_k A[m*Asm + k*Ask] * B[k*Bsk + n*Bsn]  (+ bias[n]) (+ resid[m*Csm+n*Csn])
// BM=BN=64, BK=16, 256 threads, 4x4 microtile.
__global__ __launch_bounds__(256) void gemm_kernel(
    const float* __restrict__ A, const float* __restrict__ B, float* __restrict__ C,
    const float* __restrict__ bias, const float* __restrict__ resid,
    int M, int N, int K,
    int Asm, int Ask, int Bsk, int Bsn, int Csm, int Csn) {
    __shared__ float As[16][64];
    __shared__ float Bs[16][64];
    int mtile = blockIdx.x * 64;
    int ntile = blockIdx.y * 64;
    int tid = threadIdx.x;
    int tx = tid & 15, ty = tid >> 4;
    float acc[4][4];
#pragma unroll
    for (int i = 0; i < 4; i++)
#pragma unroll
        for (int j = 0; j < 4; j++) acc[i][j] = 0.f;

    for (int k0 = 0; k0 < K; k0 += 16) {
        for (int t = tid; t < 1024; t += 256) {
            int m = t & 63, k = t >> 6;
            int gm = mtile + m, gk = k0 + k;
            As[k][m] = (gm < M && gk < K) ? A[(size_t)gm * Asm + (size_t)gk * Ask] : 0.f;
        }
        for (int t = tid; t < 1024; t += 256) {
            int n = t & 63, k = t >> 6;
            int gn = ntile + n, gk = k0 + k;
            Bs[k][n] = (gn < N && gk < K) ? B[(size_t)gk * Bsk + (size_t)gn * Bsn] : 0.f;
        }
        __syncthreads();
#pragma unroll
        for (int kk = 0; kk < 16; kk++) {
            float a[4], b[4];
#pragma unroll
            for (int i = 0; i < 4; i++) a[i] = As[kk][ty * 4 + i];
#pragma unroll
            for (int j = 0; j < 4; j++) b[j] = Bs[kk][tx * 4 + j];
#pragma unroll
            for (int i = 0; i < 4; i++)
#pragma unroll
                for (int j = 0; j < 4; j++) acc[i][j] += a[i] * b[j];
        }
        __syncthreads();
    }
#pragma unroll
    for (int i = 0; i < 4; i++) {
        int gm = mtile + ty * 4 + i;
        if (gm >= M) continue;
#pragma unroll
        for (int j = 0; j < 4; j++) {
            int gn = ntile + tx * 4 + j;
            if (gn >= N) continue;
            float v = acc[i][j];
            if (bias) v += bias[gn];
            size_t off = (size_t)gm * Csm + (size_t)gn * Csn;
            if (resid) v += resid[off];
            C[off] = v;
        }
    }
}

// ---------------- LayerNorm over 320 features ----------------
__global__ __launch_bounds__(128) void ln_kernel(const float* __restrict__ in,
                                                 const float* __restrict__ w,
                                                 const float* __restrict__ b,
                                                 float* __restrict__ out) {
    int m = blockIdx.x;
    int tid = threadIdx.x;  // 128
    const float* row = in + (size_t)m * DMODEL;
    float vals[3];
    float s = 0.f, ss = 0.f;
#pragma unroll
    for (int i = 0; i < 3; i++) {
        int c = tid + i * 128;
        float v = (c < DMODEL) ? row[c] : 0.f;
        vals[i] = v;
        s += v; ss += v * v;
    }
    __shared__ float r1[128], r2[128];
    r1[tid] = s; r2[tid] = ss;
    __syncthreads();
    for (int off = 64; off > 0; off >>= 1) {
        if (tid < off) { r1[tid] += r1[tid + off]; r2[tid] += r2[tid + off]; }
        __syncthreads();
    }
    float mu = r1[0] / (float)DMODEL;
    float var = r2[0] / (float)DMODEL - mu * mu;
    float rs = rsqrtf(var + 1e-5f);
#pragma unroll
    for (int i = 0; i < 3; i++) {
        int c = tid + i * 128;
        if (c < DMODEL) out[(size_t)m * DMODEL + c] = (vals[i] - mu) * rs * w[c] + b[c];
    }
}

// ---------------- flash attention (self + cross unified) ----------------
// Q,K,V layout [n, 320] with head h at cols [h*40, (h+1)*40). grid=(nq/128, heads), 128 thr.
__global__ __launch_bounds__(128) void attn_kernel(
    const float* __restrict__ Q, const float* __restrict__ K, const float* __restrict__ V,
    float* __restrict__ O, int n_k) {
    __shared__ float Ks[128][DH];
    __shared__ float Vs[128][DH];
    int h = blockIdx.y;
    int tid = threadIdx.x;
    int qi = blockIdx.x * 128 + tid;

    float q[DH];
#pragma unroll
    for (int d = 0; d < DH; d++) q[d] = Q[(size_t)qi * DMODEL + h * DH + d] * 0.15811388300841897f;
    float acc[DH];
#pragma unroll
    for (int d = 0; d < DH; d++) acc[d] = 0.f;
    float mi = -1e30f, li = 0.f;

    for (int kt = 0; kt < n_k; kt += 128) {
        int kcount = min(128, n_k - kt);
        for (int t = tid; t < 128 * DH; t += 128) {
            int r = t / DH, c = t % DH;
            float kv = 0.f, vv = 0.f;
            if (r < kcount) {
                size_t gk = (size_t)(kt + r) * DMODEL + h * DH + c;
                kv = K[gk]; vv = V[gk];
            }
            Ks[r][c] = kv; Vs[r][c] = vv;
        }
        __syncthreads();
        for (int j = 0; j < kcount; j += 4) {
            float s0 = 0.f, s1 = 0.f, s2 = 0.f, s3 = 0.f;
#pragma unroll
            for (int d = 0; d < DH; d++) {
                float qd = q[d];
                s0 += qd * Ks[j][d];
                s1 += qd * Ks[j + 1][d];
                s2 += qd * Ks[j + 2][d];
                s3 += qd * Ks[j + 3][d];
            }
            if (j + 1 >= kcount) s1 = -1e30f;
            if (j + 2 >= kcount) s2 = -1e30f;
            if (j + 3 >= kcount) s3 = -1e30f;
            float mnew = fmaxf(mi, fmaxf(fmaxf(s0, s1), fmaxf(s2, s3)));
            float f = __expf(mi - mnew);
            float p0 = __expf(s0 - mnew), p1 = __expf(s1 - mnew);
            float p2 = __expf(s2 - mnew), p3 = __expf(s3 - mnew);
            li = li * f + p0 + p1 + p2 + p3;
            mi = mnew;
#pragma unroll
            for (int d = 0; d < DH; d++)
                acc[d] = acc[d] * f + p0 * Vs[j][d] + p1 * Vs[j + 1][d]
                                    + p2 * Vs[j + 2][d] + p3 * Vs[j + 3][d];
        }
        __syncthreads();
    }
    float inv = 1.f / li;
#pragma unroll
    for (int d = 0; d < DH; d++) O[(size_t)qi * DMODEL + h * DH + d] = acc[d] * inv;
}

// ---------------- GEGLU elementwise ----------------
__global__ void geglu_kernel(const float* __restrict__ ff, float* __restrict__ fa) {
    int idx = blockIdx.x * 256 + threadIdx.x;
    if (idx >= NTOK * FFI) return;
    int m = idx / FFI, j = idx % FFI;
    float a = ff[(size_t)m * 2 * FFI + j];
    float g = ff[(size_t)m * 2 * FFI + FFI + j];
    float gelu = 0.5f * g * (1.f + erff(g * 0.70710678118654752f));
    fa[idx] = a * gelu;
}

// ---------------- host launch ----------------
extern "C" void kernel_launch(void* const* d_in, const int* in_sizes, int n_in,
                              void* d_out, int out_size) {
    const float* x      = (const float*)d_in[0];
    const float* ctx    = (const float*)d_in[1];
    const float* gn_w   = (const float*)d_in[2];
    const float* gn_b   = (const float*)d_in[3];
    const float* pin_w  = (const float*)d_in[4];
    const float* pin_b  = (const float*)d_in[5];
    const float* ln1_w  = (const float*)d_in[6];
    const float* ln1_b  = (const float*)d_in[7];
    const float* q1     = (const float*)d_in[8];
    const float* k1     = (const float*)d_in[9];
    const float* v1     = (const float*)d_in[10];
    const float* o1_w   = (const float*)d_in[11];
    const float* o1_b   = (const float*)d_in[12];
    const float* ln2_w  = (const float*)d_in[13];
    const float* ln2_b  = (const float*)d_in[14];
    const float* q2     = (const float*)d_in[15];
    const float* k2     = (const float*)d_in[16];
    const float* v2     = (const float*)d_in[17];
    const float* o2_w   = (const float*)d_in[18];
    const float* o2_b   = (const float*)d_in[19];
    const float* ln3_w  = (const float*)d_in[20];
    const float* ln3_b  = (const float*)d_in[21];
    const float* ff1_w  = (const float*)d_in[22];
    const float* ff1_b  = (const float*)d_in[23];
    const float* ff2_w  = (const float*)d_in[24];
    const float* ff2_b  = (const float*)d_in[25];
    const float* pout_w = (const float*)d_in[26];
    const float* pout_b = (const float*)d_in[27];
    float* out = (float*)d_out;

    float *Wp, *bp, *h, *ln, *qb, *kb, *vb, *ao, *ff, *fa;
    cudaGetSymbolAddress((void**)&Wp, g_Wp);
    cudaGetSymbolAddress((void**)&bp, g_bp);
    cudaGetSymbolAddress((void**)&h,  g_h);
    cudaGetSymbolAddress((void**)&ln, g_ln);
    cudaGetSymbolAddress((void**)&qb, g_qb);
    cudaGetSymbolAddress((void**)&kb, g_kb);
    cudaGetSymbolAddress((void**)&vb, g_vb);
    cudaGetSymbolAddress((void**)&ao, g_ao);
    cudaGetSymbolAddress((void**)&ff, g_ff);
    cudaGetSymbolAddress((void**)&fa, g_fa);

    // 1) GroupNorm stats -> per-channel affine; fold into pin conv
    gn_stats_kernel<<<32, 256>>>(x, gn_w, gn_b);
    fold_pin_kernel<<<DMODEL, 64>>>(pin_w, pin_b);

    // 2) h = GN(x) @ pin^T + bp    (x is [C, N]; output token-major [N, C])
    gemm_kernel<<<dim3(64, 5), 256>>>(x, Wp, h, bp, nullptr,
        NTOK, DMODEL, DMODEL, /*Asm*/1, /*Ask*/NTOK, /*Bsk*/1, /*Bsn*/DMODEL, DMODEL, 1);

    // 3) self-attention block
    ln_kernel<<<NTOK, 128>>>(h, ln1_w, ln1_b, ln);
    gemm_kernel<<<dim3(64, 5), 256>>>(ln, q1, qb, nullptr, nullptr,
        NTOK, DMODEL, DMODEL, DMODEL, 1, DMODEL, 1, DMODEL, 1);
    gemm_kernel<<<dim3(64, 5), 256>>>(ln, k1, kb, nullptr, nullptr,
        NTOK, DMODEL, DMODEL, DMODEL, 1, DMODEL, 1, DMODEL, 1);
    gemm_kernel<<<dim3(64, 5), 256>>>(ln, v1, vb, nullptr, nullptr,
        NTOK, DMODEL, DMODEL, DMODEL, 1, DMODEL, 1, DMODEL, 1);
    attn_kernel<<<dim3(NTOK / 128, HEADS), 128>>>(qb, kb, vb, ao, NTOK);
    gemm_kernel<<<dim3(64, 5), 256>>>(ao, o1_w, h, o1_b, h,
        NTOK, DMODEL, DMODEL, DMODEL, 1, DMODEL, 1, DMODEL, 1);

    // 4) cross-attention block
    ln_kernel<<<NTOK, 128>>>(h, ln2_w, ln2_b, ln);
    gemm_kernel<<<dim3(64, 5), 256>>>(ln, q2, qb, nullptr, nullptr,
        NTOK, DMODEL, DMODEL, DMODEL, 1, DMODEL, 1, DMODEL, 1);
    gemm_kernel<<<dim3(2, 5), 256>>>(ctx, k2, kb, nullptr, nullptr,
        CTXN, DMODEL, CTXD, CTXD, 1, DMODEL, 1, DMODEL, 1);
    gemm_kernel<<<dim3(2, 5), 256>>>(ctx, v2, vb, nullptr, nullptr,
        CTXN, DMODEL, CTXD, CTXD, 1, DMODEL, 1, DMODEL, 1);
    attn_kernel<<<dim3(NTOK / 128, HEADS), 128>>>(qb, kb, vb, ao, CTXN);
    gemm_kernel<<<dim3(64, 5), 256>>>(ao, o2_w, h, o2_b, h,
        NTOK, DMODEL, DMODEL, DMODEL, 1, DMODEL, 1, DMODEL, 1);

    // 5) GEGLU FF block
    ln_kernel<<<NTOK, 128>>>(h, ln3_w, ln3_b, ln);
    gemm_kernel<<<dim3(64, 40), 256>>>(ln, ff1_w, ff, ff1_b, nullptr,
        NTOK, 2 * FFI, DMODEL, DMODEL, 1, 2 * FFI, 1, 2 * FFI, 1);
    geglu_kernel<<<(NTOK * FFI + 255) / 256, 256>>>(ff, fa);
    gemm_kernel<<<dim3(64, 5), 256>>>(fa, ff2_w, h, ff2_b, h,
        NTOK, DMODEL, FFI, FFI, 1, DMODEL, 1, DMODEL, 1);

    // 6) output projection back to [C, H, W] + input residual
    gemm_kernel<<<dim3(64, 5), 256>>>(h, pout_w, out, pout_b, x,
        NTOK, DMODEL, DMODEL, DMODEL, 1, /*Bsk*/1, /*Bsn*/DMODEL, /*Csm*/1, /*Csn*/NTOK);
}

// round 2
// speedup vs baseline: 1.5388x; 1.5388x over previous
#include <cuda_runtime.h>
#include <cuda_bf16.h>
#include <math.h>
#include <stdint.h>

#define NTOK 4096
#define DMODEL 320
#define FFI 1280
#define HEADS 8
#define DH 40
#define CTXN 77
#define CTXD 768

// ---------------- scratch (static device globals; no allocation) ----------------
__device__ float g_s[DMODEL];
__device__ float g_t[DMODEL];
__device__ float g_Wp[DMODEL * DMODEL];     // folded pin weight, stored [c_in][c_out] (row-major B)
__device__ float g_Wq[DMODEL * DMODEL];     // pout_w transposed -> [in][out]
__device__ float g_bp[DMODEL];
__device__ float g_xt[NTOK * DMODEL];       // x transposed -> [n, c]
__device__ float g_h[NTOK * DMODEL];
__device__ float g_ln[NTOK * DMODEL];
__device__ float g_qb[NTOK * DMODEL];
__device__ float g_kb[NTOK * DMODEL];
__device__ float g_vb[NTOK * DMODEL];
__device__ float g_ao[NTOK * DMODEL];
__device__ float g_ff[NTOK * 2 * FFI];
__device__ float g_fa[NTOK * FFI];

// ---------------- GroupNorm stats ----------------
__global__ void gn_stats_kernel(const float* __restrict__ x,
                                const float* __restrict__ gn_w,
                                const float* __restrict__ gn_b) {
    int g = blockIdx.x;
    int tid = threadIdx.x;
    const float* base = x + (size_t)g * 10 * 4096;
    float s = 0.f, ss = 0.f;
    for (int i = tid; i < 40960; i += 256) {
        float v = base[i];
        s += v; ss += v * v;
    }
    __shared__ float r1[256], r2[256];
    r1[tid] = s; r2[tid] = ss;
    __syncthreads();
    for (int off = 128; off > 0; off >>= 1) {
        if (tid < off) { r1[tid] += r1[tid + off]; r2[tid] += r2[tid + off]; }
        __syncthreads();
    }
    if (tid < 10) {
        float mu = r1[0] / 40960.f;
        float var = r2[0] / 40960.f - mu * mu;
        float inv = rsqrtf(var + 1e-6f);
        int c = g * 10 + tid;
        float w = gn_w[c];
        g_s[c] = inv * w;
        g_t[c] = gn_b[c] - mu * inv * w;
    }
}

// Fold GN affine into pin weight; store TRANSPOSED: Wp[c][o] = pin_w[o][c]*s[c]
__global__ void fold_pin_kernel(const float* __restrict__ pin_w,
                                const float* __restrict__ pin_b) {
    int o = blockIdx.x;
    int tid = threadIdx.x;  // 64
    float acc = 0.f;
    for (int c = tid; c < DMODEL; c += 64) {
        float w = pin_w[o * DMODEL + c];
        g_Wp[c * DMODEL + o] = w * g_s[c];
        acc += w * g_t[c];
    }
    __shared__ float r[64];
    r[tid] = acc;
    __syncthreads();
    for (int off = 32; off > 0; off >>= 1) {
        if (tid < off) r[tid] += r[tid + off];
        __syncthreads();
    }
    if (tid == 0) g_bp[o] = pin_b[o] + r[0];
}

// ---------------- transpose: out[c][r] = in[r][c], in is [R][Cc] ----------------
__global__ void transpose_kernel(const float* __restrict__ in, float* __restrict__ out,
                                 int R, int Cc) {
    __shared__ float tile[32][33];
    int c0 = blockIdx.x * 32, r0 = blockIdx.y * 32;
    int tx = threadIdx.x, ty = threadIdx.y;  // 32 x 8
#pragma unroll
    for (int i = 0; i < 4; i++) {
        int r = r0 + ty + i * 8, c = c0 + tx;
        if (r < R && c < Cc) tile[ty + i * 8][tx] = in[(size_t)r * Cc + c];
    }
    __syncthreads();
#pragma unroll
    for (int i = 0; i < 4; i++) {
        int c = c0 + ty + i * 8, r = r0 + tx;
        if (c < Cc && r < R) out[(size_t)c * R + r] = tile[tx][ty + i * 8];
    }
}

// ---------------- tf32 tensor-core GEMM ----------------
// C[m,n] = A[m,:]@B[:,n] (+bias[n]) (+resid), A row-major lda, B row-major ldb.
// C/resid addressed with strides (Csm, Csn). BM=128, BN=64, BK=16, 128 threads, 4 warps 2x2.
__device__ __forceinline__ uint32_t f2tf32(float x) {
    uint32_t r;
    asm("cvt.rna.tf32.f32 %0, %1;" : "=r"(r) : "f"(x));
    return r;
}

__device__ __forceinline__ void mma_tf32(float* d, const uint32_t* a, const uint32_t* b) {
    asm volatile(
        "mma.sync.aligned.m16n8k8.row.col.f32.tf32.tf32.f32 "
        "{%0,%1,%2,%3}, {%4,%5,%6,%7}, {%8,%9}, {%0,%1,%2,%3};"
        : "+f"(d[0]), "+f"(d[1]), "+f"(d[2]), "+f"(d[3])
        : "r"(a[0]), "r"(a[1]), "r"(a[2]), "r"(a[3]), "r"(b[0]), "r"(b[1]));
}

__global__ __launch_bounds__(128) void gemm_tc(
    const float* __restrict__ A, const float* __restrict__ B, float* __restrict__ C,
    const float* __restrict__ bias, const float* __restrict__ resid,
    int M, int N, int K, int lda, int ldb, int Csm, int Csn) {
    __shared__ __align__(16) uint32_t As[128][20];  // [m][k], stride 20 (conflict-free)
    __shared__ __align__(16) uint32_t Bs[16][72];   // [k][n], stride 72 (conflict-free)
    int tid = threadIdx.x;
    int warp = tid >> 5, lane = tid & 31;
    int grp = lane >> 2, t4 = lane & 3;
    int m0 = blockIdx.x * 128, n0 = blockIdx.y * 64;
    int wm = (warp >> 1) * 64, wn = (warp & 1) * 32;

    float acc[4][4][4];
#pragma unroll
    for (int mi = 0; mi < 4; mi++)
#pragma unroll
        for (int ni = 0; ni < 4; ni++)
#pragma unroll
            for (int r = 0; r < 4; r++) acc[mi][ni][r] = 0.f;

    for (int k0 = 0; k0 < K; k0 += 16) {
        // A tile: row per thread, 16 k-values = 4 float4
        int ar = m0 + tid;
        const float4* arow = (const float4*)(A + (size_t)ar * lda + k0);
#pragma unroll
        for (int i = 0; i < 4; i++) {
            float4 v = make_float4(0.f, 0.f, 0.f, 0.f);
            if (ar < M) v = arow[i];
            uint4 u;
            u.x = f2tf32(v.x); u.y = f2tf32(v.y); u.z = f2tf32(v.z); u.w = f2tf32(v.w);
            *(uint4*)&As[tid][i * 4] = u;
        }
        // B tile: 16 rows x 64 cols = 256 float4, 2 per thread
#pragma unroll
        for (int i = 0; i < 2; i++) {
            int f = tid + i * 128;
            int bk = f >> 4, bn = (f & 15) * 4;
            float4 v = *(const float4*)(B + (size_t)(k0 + bk) * ldb + n0 + bn);
            uint4 u;
            u.x = f2tf32(v.x); u.y = f2tf32(v.y); u.z = f2tf32(v.z); u.w = f2tf32(v.w);
            *(uint4*)&Bs[bk][bn] = u;
        }
        __syncthreads();
#pragma unroll
        for (int kk = 0; kk < 16; kk += 8) {
            uint32_t af[4][4];
#pragma unroll
            for (int mi = 0; mi < 4; mi++) {
                int rm = wm + mi * 16;
                af[mi][0] = As[rm + grp][kk + t4];
                af[mi][1] = As[rm + grp + 8][kk + t4];
                af[mi][2] = As[rm + grp][kk + t4 + 4];
                af[mi][3] = As[rm + grp + 8][kk + t4 + 4];
            }
            uint32_t bf[4][2];
#pragma unroll
            for (int ni = 0; ni < 4; ni++) {
                int cn = wn + ni * 8 + grp;
                bf[ni][0] = Bs[kk + t4][cn];
                bf[ni][1] = Bs[kk + t4 + 4][cn];
            }
#pragma unroll
            for (int mi = 0; mi < 4; mi++)
#pragma unroll
                for (int ni = 0; ni < 4; ni++)
                    mma_tf32(acc[mi][ni], af[mi], bf[ni]);
        }
        __syncthreads();
    }
    // epilogue
#pragma unroll
    for (int mi = 0; mi < 4; mi++) {
        int r0r = m0 + wm + mi * 16 + grp;
        int r1r = r0r + 8;
#pragma unroll
        for (int ni = 0; ni < 4; ni++) {
            int c = n0 + wn + ni * 8 + t4 * 2;
            float b0 = bias ? bias[c] : 0.f;
            float b1 = bias ? bias[c + 1] : 0.f;
            if (r0r < M) {
                size_t o0 = (size_t)r0r * Csm + (size_t)c * Csn;
                size_t o1 = o0 + Csn;
                float v0 = acc[mi][ni][0] + b0;
                float v1 = acc[mi][ni][1] + b1;
                if (resid) { v0 += resid[o0]; v1 += resid[o1]; }
                C[o0] = v0; C[o1] = v1;
            }
            if (r1r < M) {
                size_t o0 = (size_t)r1r * Csm + (size_t)c * Csn;
                size_t o1 = o0 + Csn;
                float v0 = acc[mi][ni][2] + b0;
                float v1 = acc[mi][ni][3] + b1;
                if (resid) { v0 += resid[o0]; v1 += resid[o1]; }
                C[o0] = v0; C[o1] = v1;
            }
        }
    }
}

// ---------------- LayerNorm ----------------
__global__ __launch_bounds__(128) void ln_kernel(const float* __restrict__ in,
                                                 const float* __restrict__ w,
                                                 const float* __restrict__ b,
                                                 float* __restrict__ out) {
    int m = blockIdx.x;
    int tid = threadIdx.x;
    const float* row = in + (size_t)m * DMODEL;
    float vals[3];
    float s = 0.f, ss = 0.f;
#pragma unroll
    for (int i = 0; i < 3; i++) {
        int c = tid + i * 128;
        float v = (c < DMODEL) ? row[c] : 0.f;
        vals[i] = v;
        s += v; ss += v * v;
    }
    __shared__ float r1[128], r2[128];
    r1[tid] = s; r2[tid] = ss;
    __syncthreads();
    for (int off = 64; off > 0; off >>= 1) {
        if (tid < off) { r1[tid] += r1[tid + off]; r2[tid] += r2[tid + off]; }
        __syncthreads();
    }
    float mu = r1[0] / (float)DMODEL;
    float var = r2[0] / (float)DMODEL - mu * mu;
    float rs = rsqrtf(var + 1e-5f);
#pragma unroll
    for (int i = 0; i < 3; i++) {
        int c = tid + i * 128;
        if (c < DMODEL) out[(size_t)m * DMODEL + c] = (vals[i] - mu) * rs * w[c] + b[c];
    }
}

// ---------------- flash attention: 2 queries/thread, 256 q per block ----------------
__global__ __launch_bounds__(128) void attn_kernel(
    const float* __restrict__ Q, const float* __restrict__ K, const float* __restrict__ V,
    float* __restrict__ O, int n_k) {
    __shared__ float Ks[128][DH];
    __shared__ float Vs[128][DH];
    int h = blockIdx.y;
    int tid = threadIdx.x;
    int qi0 = blockIdx.x * 256 + tid;
    int qi1 = qi0 + 128;

    float q0[DH], q1[DH], a0[DH], a1[DH];
#pragma unroll
    for (int d = 0; d < DH; d++) {
        q0[d] = Q[(size_t)qi0 * DMODEL + h * DH + d] * 0.15811388300841897f;
        q1[d] = Q[(size_t)qi1 * DMODEL + h * DH + d] * 0.15811388300841897f;
        a0[d] = 0.f; a1[d] = 0.f;
    }
    float m0 = -1e30f, l0 = 0.f, m1 = -1e30f, l1 = 0.f;

    for (int kt = 0; kt < n_k; kt += 128) {
        int kcount = min(128, n_k - kt);
        for (int t = tid; t < 128 * DH; t += 128) {
            int r = t / DH, c = t % DH;
            float kv = 0.f, vv = 0.f;
            if (r < kcount) {
                size_t gk = (size_t)(kt + r) * DMODEL + h * DH + c;
                kv = K[gk]; vv = V[gk];
            }
            Ks[r][c] = kv; Vs[r][c] = vv;
        }
        __syncthreads();
        for (int j = 0; j < kcount; j += 4) {
            float s0[4] = {0.f, 0.f, 0.f, 0.f};
            float s1[4] = {0.f, 0.f, 0.f, 0.f};
#pragma unroll
            for (int d = 0; d < DH; d++) {
                float k0v = Ks[j][d], k1v = Ks[j + 1][d];
                float k2v = Ks[j + 2][d], k3v = Ks[j + 3][d];
                float qa = q0[d], qb = q1[d];
                s0[0] += qa * k0v; s0[1] += qa * k1v; s0[2] += qa * k2v; s0[3] += qa * k3v;
                s1[0] += qb * k0v; s1[1] += qb * k1v; s1[2] += qb * k2v; s1[3] += qb * k3v;
            }
            if (j + 1 >= kcount) { s0[1] = -1e30f; s1[1] = -1e30f; }
            if (j + 2 >= kcount) { s0[2] = -1e30f; s1[2] = -1e30f; }
            if (j + 3 >= kcount) { s0[3] = -1e30f; s1[3] = -1e30f; }

            float mn0 = fmaxf(m0, fmaxf(fmaxf(s0[0], s0[1]), fmaxf(s0[2], s0[3])));
            float f0 = __expf(m0 - mn0);
            float p00 = __expf(s0[0] - mn0), p01 = __expf(s0[1] - mn0);
            float p02 = __expf(s0[2] - mn0), p03 = __expf(s0[3] - mn0);
            l0 = l0 * f0 + p00 + p01 + p02 + p03;
            m0 = mn0;

            float mn1 = fmaxf(m1, fmaxf(fmaxf(s1[0], s1[1]), fmaxf(s1[2], s1[3])));
            float f1 = __expf(m1 - mn1);
            float p10 = __expf(s1[0] - mn1), p11 = __expf(s1[1] - mn1);
            float p12 = __expf(s1[2] - mn1), p13 = __expf(s1[3] - mn1);
            l1 = l1 * f1 + p10 + p11 + p12 + p13;
            m1 = mn1;

#pragma unroll
            for (int d = 0; d < DH; d++) {
                float v0 = Vs[j][d], v1 = Vs[j + 1][d];
                float v2 = Vs[j + 2][d], v3 = Vs[j + 3][d];
                a0[d] = a0[d] * f0 + p00 * v0 + p01 * v1 + p02 * v2 + p03 * v3;
                a1[d] = a1[d] * f1 + p10 * v0 + p11 * v1 + p12 * v2 + p13 * v3;
            }
        }
        __syncthreads();
    }
    float inv0 = 1.f / l0, inv1 = 1.f / l1;
#pragma unroll
    for (int d = 0; d < DH; d++) {
        O[(size_t)qi0 * DMODEL + h * DH + d] = a0[d] * inv0;
        O[(size_t)qi1 * DMODEL + h * DH + d] = a1[d] * inv1;
    }
}

// ---------------- GEGLU ----------------
__global__ void geglu_kernel(const float* __restrict__ ff, float* __restrict__ fa) {
    int idx = blockIdx.x * 256 + threadIdx.x;
    if (idx >= NTOK * FFI) return;
    int m = idx / FFI, j = idx % FFI;
    float a = ff[(size_t)m * 2 * FFI + j];
    float g = ff[(size_t)m * 2 * FFI + FFI + j];
    float gelu = 0.5f * g * (1.f + erff(g * 0.70710678118654752f));
    fa[idx] = a * gelu;
}

// ---------------- host launch ----------------
extern "C" void kernel_launch(void* const* d_in, const int* in_sizes, int n_in,
                              void* d_out, int out_size) {
    const float* x      = (const float*)d_in[0];
    const float* ctx    = (const float*)d_in[1];
    const float* gn_w   = (const float*)d_in[2];
    const float* gn_b   = (const float*)d_in[3];
    const float* pin_w  = (const float*)d_in[4];
    const float* pin_b  = (const float*)d_in[5];
    const float* ln1_w  = (const float*)d_in[6];
    const float* ln1_b  = (const float*)d_in[7];
    const float* q1     = (const float*)d_in[8];
    const float* k1     = (const float*)d_in[9];
    const float* v1     = (const float*)d_in[10];
    const float* o1_w   = (const float*)d_in[11];
    const float* o1_b   = (const float*)d_in[12];
    const float* ln2_w  = (const float*)d_in[13];
    const float* ln2_b  = (const float*)d_in[14];
    const float* q2     = (const float*)d_in[15];
    const float* k2     = (const float*)d_in[16];
    const float* v2     = (const float*)d_in[17];
    const float* o2_w   = (const float*)d_in[18];
    const float* o2_b   = (const float*)d_in[19];
    const float* ln3_w  = (const float*)d_in[20];
    const float* ln3_b  = (const float*)d_in[21];
    const float* ff1_w  = (const float*)d_in[22];
    const float* ff1_b  = (const float*)d_in[23];
    const float* ff2_w  = (const float*)d_in[24];
    const float* ff2_b  = (const float*)d_in[25];
    const float* pout_w = (const float*)d_in[26];
    const float* pout_b = (const float*)d_in[27];
    float* out = (float*)d_out;

    float *Wp, *Wq, *bp, *xt, *h, *ln, *qb, *kb, *vb, *ao, *ff, *fa;
    cudaGetSymbolAddress((void**)&Wp, g_Wp);
    cudaGetSymbolAddress((void**)&Wq, g_Wq);
    cudaGetSymbolAddress((void**)&bp, g_bp);
    cudaGetSymbolAddress((void**)&xt, g_xt);
    cudaGetSymbolAddress((void**)&h,  g_h);
    cudaGetSymbolAddress((void**)&ln, g_ln);
    cudaGetSymbolAddress((void**)&qb, g_qb);
    cudaGetSymbolAddress((void**)&kb, g_kb);
    cudaGetSymbolAddress((void**)&vb, g_vb);
    cudaGetSymbolAddress((void**)&ao, g_ao);
    cudaGetSymbolAddress((void**)&ff, g_ff);
    cudaGetSymbolAddress((void**)&fa, g_fa);

    // prep: GN stats, fold pin (transposed), transpose x and pout_w
    gn_stats_kernel<<<32, 256>>>(x, gn_w, gn_b);
    fold_pin_kernel<<<DMODEL, 64>>>(pin_w, pin_b);
    transpose_kernel<<<dim3(128, 10), dim3(32, 8)>>>(x, xt, DMODEL, NTOK);       // xt[n][c]
    transpose_kernel<<<dim3(10, 10), dim3(32, 8)>>>(pout_w, Wq, DMODEL, DMODEL); // Wq[in][out]

    // 1) h = GN(x) @ pin^T + bp   (token-major)
    gemm_tc<<<dim3(32, 5), 128>>>(xt, Wp, h, bp, nullptr,
        NTOK, DMODEL, DMODEL, DMODEL, DMODEL, DMODEL, 1);

    // 2) self-attention block
    ln_kernel<<<NTOK, 128>>>(h, ln1_w, ln1_b, ln);
    gemm_tc<<<dim3(32, 5), 128>>>(ln, q1, qb, nullptr, nullptr,
        NTOK, DMODEL, DMODEL, DMODEL, DMODEL, DMODEL, 1);
    gemm_tc<<<dim3(32, 5), 128>>>(ln, k1, kb, nullptr, nullptr,
        NTOK, DMODEL, DMODEL, DMODEL, DMODEL, DMODEL, 1);
    gemm_tc<<<dim3(32, 5), 128>>>(ln, v1, vb, nullptr, nullptr,
        NTOK, DMODEL, DMODEL, DMODEL, DMODEL, DMODEL, 1);
    attn_kernel<<<dim3(NTOK / 256, HEADS), 128>>>(qb, kb, vb, ao, NTOK);
    gemm_tc<<<dim3(32, 5), 128>>>(ao, o1_w, h, o1_b, h,
        NTOK, DMODEL, DMODEL, DMODEL, DMODEL, DMODEL, 1);

    // 3) cross-attention block
    ln_kernel<<<NTOK, 128>>>(h, ln2_w, ln2_b, ln);
    gemm_tc<<<dim3(32, 5), 128>>>(ln, q2, qb, nullptr, nullptr,
        NTOK, DMODEL, DMODEL, DMODEL, DMODEL, DMODEL, 1);
    gemm_tc<<<dim3(1, 5), 128>>>(ctx, k2, kb, nullptr, nullptr,
        CTXN, DMODEL, CTXD, CTXD, DMODEL, DMODEL, 1);
    gemm_tc<<<dim3(1, 5), 128>>>(ctx, v2, vb, nullptr, nullptr,
        CTXN, DMODEL, CTXD, CTXD, DMODEL, DMODEL, 1);
    attn_kernel<<<dim3(NTOK / 256, HEADS), 128>>>(qb, kb, vb, ao, CTXN);
    gemm_tc<<<dim3(32, 5), 128>>>(ao, o2_w, h, o2_b, h,
        NTOK, DMODEL, DMODEL, DMODEL, DMODEL, DMODEL, 1);

    // 4) GEGLU FF block
    ln_kernel<<<NTOK, 128>>>(h, ln3_w, ln3_b, ln);
    gemm_tc<<<dim3(32, 40), 128>>>(ln, ff1_w, ff, ff1_b, nullptr,
        NTOK, 2 * FFI, DMODEL, DMODEL, 2 * FFI, 2 * FFI, 1);
    geglu_kernel<<<(NTOK * FFI + 255) / 256, 256>>>(ff, fa);
    gemm_tc<<<dim3(32, 5), 128>>>(fa, ff2_w, h, ff2_b, h,
        NTOK, DMODEL, FFI, FFI, DMODEL, DMODEL, 1);

    // 5) output projection, transposed store back to [C, H, W] + input residual
    gemm_tc<<<dim3(32, 5), 128>>>(h, Wq, out, pout_b, x,
        NTOK, DMODEL, DMODEL, DMODEL, DMODEL, 1, NTOK);
}

// round 3
// speedup vs baseline: 2.4599x; 1.5986x over previous
#include <cuda_runtime.h>
#include <cuda_bf16.h>
#include <math.h>
#include <stdint.h>

#define NTOK 4096
#define DMODEL 320
#define FFI 1280
#define HEADS 8
#define DH 40
#define CTXN 77
#define CTXD 768

// ---------------- scratch (static device globals; no allocation) ----------------
__device__ float g_s[DMODEL];
__device__ float g_t[DMODEL];
__device__ float g_Wp[DMODEL * DMODEL];     // folded pin weight, [c_in][c_out]
__device__ float g_Wq[DMODEL * DMODEL];     // pout_w transposed -> [in][out]
__device__ float g_bp[DMODEL];
__device__ float g_xt[NTOK * DMODEL];       // x transposed -> [n, c]
__device__ float g_h[NTOK * DMODEL];
__device__ float g_ln[NTOK * DMODEL];
__device__ float g_qb[NTOK * DMODEL];
__device__ float g_kb[NTOK * DMODEL];
__device__ float g_vb[NTOK * DMODEL];
__device__ float g_ao[NTOK * DMODEL];
__device__ float g_ff[NTOK * 2 * FFI];
__device__ float g_fa[NTOK * FFI];

// ---------------- GroupNorm stats ----------------
__global__ void gn_stats_kernel(const float* __restrict__ x,
                                const float* __restrict__ gn_w,
                                const float* __restrict__ gn_b) {
    int g = blockIdx.x;
    int tid = threadIdx.x;
    const float* base = x + (size_t)g * 10 * 4096;
    float s = 0.f, ss = 0.f;
    for (int i = tid; i < 40960; i += 256) {
        float v = base[i];
        s += v; ss += v * v;
    }
    __shared__ float r1[256], r2[256];
    r1[tid] = s; r2[tid] = ss;
    __syncthreads();
    for (int off = 128; off > 0; off >>= 1) {
        if (tid < off) { r1[tid] += r1[tid + off]; r2[tid] += r2[tid + off]; }
        __syncthreads();
    }
    if (tid < 10) {
        float mu = r1[0] / 40960.f;
        float var = r2[0] / 40960.f - mu * mu;
        float inv = rsqrtf(var + 1e-6f);
        int c = g * 10 + tid;
        float w = gn_w[c];
        g_s[c] = inv * w;
        g_t[c] = gn_b[c] - mu * inv * w;
    }
}

__global__ void fold_pin_kernel(const float* __restrict__ pin_w,
                                const float* __restrict__ pin_b) {
    int o = blockIdx.x;
    int tid = threadIdx.x;  // 64
    float acc = 0.f;
    for (int c = tid; c < DMODEL; c += 64) {
        float w = pin_w[o * DMODEL + c];
        g_Wp[c * DMODEL + o] = w * g_s[c];
        acc += w * g_t[c];
    }
    __shared__ float r[64];
    r[tid] = acc;
    __syncthreads();
    for (int off = 32; off > 0; off >>= 1) {
        if (tid < off) r[tid] += r[tid + off];
        __syncthreads();
    }
    if (tid == 0) g_bp[o] = pin_b[o] + r[0];
}

// ---------------- transpose ----------------
__global__ void transpose_kernel(const float* __restrict__ in, float* __restrict__ out,
                                 int R, int Cc) {
    __shared__ float tile[32][33];
    int c0 = blockIdx.x * 32, r0 = blockIdx.y * 32;
    int tx = threadIdx.x, ty = threadIdx.y;
#pragma unroll
    for (int i = 0; i < 4; i++) {
        int r = r0 + ty + i * 8, c = c0 + tx;
        if (r < R && c < Cc) tile[ty + i * 8][tx] = in[(size_t)r * Cc + c];
    }
    __syncthreads();
#pragma unroll
    for (int i = 0; i < 4; i++) {
        int c = c0 + ty + i * 8, r = r0 + tx;
        if (c < Cc && r < R) out[(size_t)c * R + r] = tile[tx][ty + i * 8];
    }
}

// ---------------- tf32 helpers ----------------
__device__ __forceinline__ uint32_t f2tf32(float x) {
    uint32_t r;
    asm("cvt.rna.tf32.f32 %0, %1;" : "=r"(r) : "f"(x));
    return r;
}

__device__ __forceinline__ void mma_tf32(float* d, const uint32_t* a, const uint32_t* b) {
    asm volatile(
        "mma.sync.aligned.m16n8k8.row.col.f32.tf32.tf32.f32 "
        "{%0,%1,%2,%3}, {%4,%5,%6,%7}, {%8,%9}, {%0,%1,%2,%3};"
        : "+f"(d[0]), "+f"(d[1]), "+f"(d[2]), "+f"(d[3])
        : "r"(a[0]), "r"(a[1]), "r"(a[2]), "r"(a[3]), "r"(b[0]), "r"(b[1]));
}

// ---------------- tf32 tensor-core GEMM ----------------
__global__ __launch_bounds__(128) void gemm_tc(
    const float* __restrict__ A, const float* __restrict__ B, float* __restrict__ C,
    const float* __restrict__ bias, const float* __restrict__ resid,
    int M, int N, int K, int lda, int ldb, int Csm, int Csn) {
    __shared__ __align__(16) uint32_t As[128][20];
    __shared__ __align__(16) uint32_t Bs[16][72];
    int tid = threadIdx.x;
    int warp = tid >> 5, lane = tid & 31;
    int grp = lane >> 2, t4 = lane & 3;
    int m0 = blockIdx.x * 128, n0 = blockIdx.y * 64;
    int wm = (warp >> 1) * 64, wn = (warp & 1) * 32;

    float acc[4][4][4];
#pragma unroll
    for (int mi = 0; mi < 4; mi++)
#pragma unroll
        for (int ni = 0; ni < 4; ni++)
#pragma unroll
            for (int r = 0; r < 4; r++) acc[mi][ni][r] = 0.f;

    for (int k0 = 0; k0 < K; k0 += 16) {
        int ar = m0 + tid;
        const float4* arow = (const float4*)(A + (size_t)ar * lda + k0);
#pragma unroll
        for (int i = 0; i < 4; i++) {
            float4 v = make_float4(0.f, 0.f, 0.f, 0.f);
            if (ar < M) v = arow[i];
            uint4 u;
            u.x = f2tf32(v.x); u.y = f2tf32(v.y); u.z = f2tf32(v.z); u.w = f2tf32(v.w);
            *(uint4*)&As[tid][i * 4] = u;
        }
#pragma unroll
        for (int i = 0; i < 2; i++) {
            int f = tid + i * 128;
            int bk = f >> 4, bn = (f & 15) * 4;
            float4 v = *(const float4*)(B + (size_t)(k0 + bk) * ldb + n0 + bn);
            uint4 u;
            u.x = f2tf32(v.x); u.y = f2tf32(v.y); u.z = f2tf32(v.z); u.w = f2tf32(v.w);
            *(uint4*)&Bs[bk][bn] = u;
        }
        __syncthreads();
#pragma unroll
        for (int kk = 0; kk < 16; kk += 8) {
            uint32_t af[4][4];
#pragma unroll
            for (int mi = 0; mi < 4; mi++) {
                int rm = wm + mi * 16;
                af[mi][0] = As[rm + grp][kk + t4];
                af[mi][1] = As[rm + grp + 8][kk + t4];
                af[mi][2] = As[rm + grp][kk + t4 + 4];
                af[mi][3] = As[rm + grp + 8][kk + t4 + 4];
            }
            uint32_t bf[4][2];
#pragma unroll
            for (int ni = 0; ni < 4; ni++) {
                int cn = wn + ni * 8 + grp;
                bf[ni][0] = Bs[kk + t4][cn];
                bf[ni][1] = Bs[kk + t4 + 4][cn];
            }
#pragma unroll
            for (int mi = 0; mi < 4; mi++)
#pragma unroll
                for (int ni = 0; ni < 4; ni++)
                    mma_tf32(acc[mi][ni], af[mi], bf[ni]);
        }
        __syncthreads();
    }
#pragma unroll
    for (int mi = 0; mi < 4; mi++) {
        int r0r = m0 + wm + mi * 16 + grp;
        int r1r = r0r + 8;
#pragma unroll
        for (int ni = 0; ni < 4; ni++) {
            int c = n0 + wn + ni * 8 + t4 * 2;
            float b0 = bias ? bias[c] : 0.f;
            float b1 = bias ? bias[c + 1] : 0.f;
            if (r0r < M) {
                size_t o0 = (size_t)r0r * Csm + (size_t)c * Csn;
                size_t o1 = o0 + Csn;
                float v0 = acc[mi][ni][0] + b0;
                float v1 = acc[mi][ni][1] + b1;
                if (resid) { v0 += resid[o0]; v1 += resid[o1]; }
                C[o0] = v0; C[o1] = v1;
            }
            if (r1r < M) {
                size_t o0 = (size_t)r1r * Csm + (size_t)c * Csn;
                size_t o1 = o0 + Csn;
                float v0 = acc[mi][ni][2] + b0;
                float v1 = acc[mi][ni][3] + b1;
                if (resid) { v0 += resid[o0]; v1 += resid[o1]; }
                C[o0] = v0; C[o1] = v1;
            }
        }
    }
}

// ---------------- LayerNorm ----------------
__global__ __launch_bounds__(128) void ln_kernel(const float* __restrict__ in,
                                                 const float* __restrict__ w,
                                                 const float* __restrict__ b,
                                                 float* __restrict__ out) {
    int m = blockIdx.x;
    int tid = threadIdx.x;
    const float* row = in + (size_t)m * DMODEL;
    float vals[3];
    float s = 0.f, ss = 0.f;
#pragma unroll
    for (int i = 0; i < 3; i++) {
        int c = tid + i * 128;
        float v = (c < DMODEL) ? row[c] : 0.f;
        vals[i] = v;
        s += v; ss += v * v;
    }
    __shared__ float r1[128], r2[128];
    r1[tid] = s; r2[tid] = ss;
    __syncthreads();
    for (int off = 64; off > 0; off >>= 1) {
        if (tid < off) { r1[tid] += r1[tid + off]; r2[tid] += r2[tid + off]; }
        __syncthreads();
    }
    float mu = r1[0] / (float)DMODEL;
    float var = r2[0] / (float)DMODEL - mu * mu;
    float rs = rsqrtf(var + 1e-5f);
#pragma unroll
    for (int i = 0; i < 3; i++) {
        int c = tid + i * 128;
        if (c < DMODEL) out[(size_t)m * DMODEL + c] = (vals[i] - mu) * rs * w[c] + b[c];
    }
}

// ---------------- tensor-core flash attention ----------------
// Block: 64 queries x 1 head. 4 warps, each owns 16 query rows.
// S = Q@K^T via m16n8k8 tf32 mma, online softmax on fragments, P@V via mma.
__global__ __launch_bounds__(128) void attn_tc(
    const float* __restrict__ Q, const float* __restrict__ K, const float* __restrict__ V,
    float* __restrict__ O, int n_k) {
    __shared__ __align__(16) uint32_t Ks[DH][72];    // K^T tile [d][key], stride 72 (CF)
    __shared__ __align__(16) uint32_t Vs[64][DH];    // V tile [key][d], stride 40 (CF)
    __shared__ __align__(16) uint32_t Ps[64][68];    // P tile tf32, stride 68 (CF)

    int h = blockIdx.y;
    int m0 = blockIdx.x * 64;
    int tid = threadIdx.x;
    int warp = tid >> 5, lane = tid & 31;
    int grp = lane >> 2, t4 = lane & 3;
    int wm = warp * 16;
    int row0 = m0 + wm + grp, row1 = row0 + 8;

    const float scale = 0.15811388300841897f;
    // Q fragments: 5 k-tiles of 8, loaded once
    uint32_t qf[5][4];
#pragma unroll
    for (int kt = 0; kt < 5; kt++) {
        int c = kt * 8 + t4;
        qf[kt][0] = f2tf32(Q[(size_t)row0 * DMODEL + h * DH + c] * scale);
        qf[kt][1] = f2tf32(Q[(size_t)row1 * DMODEL + h * DH + c] * scale);
        qf[kt][2] = f2tf32(Q[(size_t)row0 * DMODEL + h * DH + c + 4] * scale);
        qf[kt][3] = f2tf32(Q[(size_t)row1 * DMODEL + h * DH + c + 4] * scale);
    }

    float o[5][4];
#pragma unroll
    for (int d = 0; d < 5; d++)
#pragma unroll
        for (int r = 0; r < 4; r++) o[d][r] = 0.f;
    float m_r0 = -1e30f, m_r1 = -1e30f, l_r0 = 0.f, l_r1 = 0.f;

    for (int kt0 = 0; kt0 < n_k; kt0 += 64) {
        int kcount = min(64, n_k - kt0);
        // load K^T (transposed) and V tiles
        for (int t = tid; t < 64 * DH; t += 128) {
            int r = t / DH, c = t % DH;
            float kv = 0.f, vv = 0.f;
            if (r < kcount) {
                size_t g = (size_t)(kt0 + r) * DMODEL + h * DH + c;
                kv = K[g]; vv = V[g];
            }
            Ks[c][r] = f2tf32(kv);
            Vs[r][c] = f2tf32(vv);
        }
        __syncthreads();

        // S = Q @ K^T : 8 n-tiles of 8 keys
        float s[8][4];
#pragma unroll
        for (int nt = 0; nt < 8; nt++)
#pragma unroll
            for (int r = 0; r < 4; r++) s[nt][r] = 0.f;
#pragma unroll
        for (int kt = 0; kt < 5; kt++) {
#pragma unroll
            for (int nt = 0; nt < 8; nt++) {
                uint32_t bf[2];
                bf[0] = Ks[kt * 8 + t4][nt * 8 + grp];
                bf[1] = Ks[kt * 8 + t4 + 4][nt * 8 + grp];
                mma_tf32(s[nt], qf[kt], bf);
            }
        }
        // mask tail columns (cross-attn)
        if (kcount < 64) {
#pragma unroll
            for (int nt = 0; nt < 8; nt++) {
                int c0 = nt * 8 + 2 * t4;
                if (c0 >= kcount)     { s[nt][0] = -1e30f; s[nt][2] = -1e30f; }
                if (c0 + 1 >= kcount) { s[nt][1] = -1e30f; s[nt][3] = -1e30f; }
            }
        }

        // online softmax on fragments
        float mx0 = m_r0, mx1 = m_r1;
#pragma unroll
        for (int nt = 0; nt < 8; nt++) {
            mx0 = fmaxf(mx0, fmaxf(s[nt][0], s[nt][1]));
            mx1 = fmaxf(mx1, fmaxf(s[nt][2], s[nt][3]));
        }
        mx0 = fmaxf(mx0, __shfl_xor_sync(0xffffffffu, mx0, 1));
        mx0 = fmaxf(mx0, __shfl_xor_sync(0xffffffffu, mx0, 2));
        mx1 = fmaxf(mx1, __shfl_xor_sync(0xffffffffu, mx1, 1));
        mx1 = fmaxf(mx1, __shfl_xor_sync(0xffffffffu, mx1, 2));
        float f0 = __expf(m_r0 - mx0), f1 = __expf(m_r1 - mx1);
        float sum0 = 0.f, sum1 = 0.f;
#pragma unroll
        for (int nt = 0; nt < 8; nt++) {
            float p0 = __expf(s[nt][0] - mx0);
            float p1 = __expf(s[nt][1] - mx0);
            float p2 = __expf(s[nt][2] - mx1);
            float p3 = __expf(s[nt][3] - mx1);
            sum0 += p0 + p1; sum1 += p2 + p3;
            int c = nt * 8 + 2 * t4;
            Ps[wm + grp][c] = f2tf32(p0);
            Ps[wm + grp][c + 1] = f2tf32(p1);
            Ps[wm + grp + 8][c] = f2tf32(p2);
            Ps[wm + grp + 8][c + 1] = f2tf32(p3);
        }
        sum0 += __shfl_xor_sync(0xffffffffu, sum0, 1);
        sum0 += __shfl_xor_sync(0xffffffffu, sum0, 2);
        sum1 += __shfl_xor_sync(0xffffffffu, sum1, 1);
        sum1 += __shfl_xor_sync(0xffffffffu, sum1, 2);
        l_r0 = l_r0 * f0 + sum0; m_r0 = mx0;
        l_r1 = l_r1 * f1 + sum1; m_r1 = mx1;

        // rescale accumulator
#pragma unroll
        for (int d = 0; d < 5; d++) {
            o[d][0] *= f0; o[d][1] *= f0;
            o[d][2] *= f1; o[d][3] *= f1;
        }
        __syncwarp();

        // load P fragments (warp-private rows) once
        uint32_t pa[8][4];
#pragma unroll
        for (int ks = 0; ks < 8; ks++) {
            pa[ks][0] = Ps[wm + grp][ks * 8 + t4];
            pa[ks][1] = Ps[wm + grp + 8][ks * 8 + t4];
            pa[ks][2] = Ps[wm + grp][ks * 8 + t4 + 4];
            pa[ks][3] = Ps[wm + grp + 8][ks * 8 + t4 + 4];
        }
        // O += P @ V : 5 n-tiles (dh) x 8 k-steps (keys)
#pragma unroll
        for (int d = 0; d < 5; d++) {
#pragma unroll
            for (int ks = 0; ks < 8; ks++) {
                uint32_t bf[2];
                bf[0] = Vs[ks * 8 + t4][d * 8 + grp];
                bf[1] = Vs[ks * 8 + t4 + 4][d * 8 + grp];
                mma_tf32(o[d], pa[ks], bf);
            }
        }
        __syncthreads();
    }

    float inv0 = 1.f / l_r0, inv1 = 1.f / l_r1;
#pragma unroll
    for (int d = 0; d < 5; d++) {
        int c = h * DH + d * 8 + 2 * t4;
        O[(size_t)row0 * DMODEL + c]     = o[d][0] * inv0;
        O[(size_t)row0 * DMODEL + c + 1] = o[d][1] * inv0;
        O[(size_t)row1 * DMODEL + c]     = o[d][2] * inv1;
        O[(size_t)row1 * DMODEL + c + 1] = o[d][3] * inv1;
    }
}

// ---------------- GEGLU ----------------
__global__ void geglu_kernel(const float* __restrict__ ff, float* __restrict__ fa) {
    int idx = blockIdx.x * 256 + threadIdx.x;
    if (idx >= NTOK * FFI) return;
    int m = idx / FFI, j = idx % FFI;
    float a = ff[(size_t)m * 2 * FFI + j];
    float g = ff[(size_t)m * 2 * FFI + FFI + j];
    float gelu = 0.5f * g * (1.f + erff(g * 0.70710678118654752f));
    fa[idx] = a * gelu;
}

// ---------------- host launch ----------------
extern "C" void kernel_launch(void* const* d_in, const int* in_sizes, int n_in,
                              void* d_out, int out_size) {
    const float* x      = (const float*)d_in[0];
    const float* ctx    = (const float*)d_in[1];
    const float* gn_w   = (const float*)d_in[2];
    const float* gn_b   = (const float*)d_in[3];
    const float* pin_w  = (const float*)d_in[4];
    const float* pin_b  = (const float*)d_in[5];
    const float* ln1_w  = (const float*)d_in[6];
    const float* ln1_b  = (const float*)d_in[7];
    const float* q1     = (const float*)d_in[8];
    const float* k1     = (const float*)d_in[9];
    const float* v1     = (const float*)d_in[10];
    const float* o1_w   = (const float*)d_in[11];
    const float* o1_b   = (const float*)d_in[12];
    const float* ln2_w  = (const float*)d_in[13];
    const float* ln2_b  = (const float*)d_in[14];
    const float* q2     = (const float*)d_in[15];
    const float* k2     = (const float*)d_in[16];
    const float* v2     = (const float*)d_in[17];
    const float* o2_w   = (const float*)d_in[18];
    const float* o2_b   = (const float*)d_in[19];
    const float* ln3_w  = (const float*)d_in[20];
    const float* ln3_b  = (const float*)d_in[21];
    const float* ff1_w  = (const float*)d_in[22];
    const float* ff1_b  = (const float*)d_in[23];
    const float* ff2_w  = (const float*)d_in[24];
    const float* ff2_b  = (const float*)d_in[25];
    const float* pout_w = (const float*)d_in[26];
    const float* pout_b = (const float*)d_in[27];
    float* out = (float*)d_out;

    float *Wp, *Wq, *bp, *xt, *h, *ln, *qb, *kb, *vb, *ao, *ff, *fa;
    cudaGetSymbolAddress((void**)&Wp, g_Wp);
    cudaGetSymbolAddress((void**)&Wq, g_Wq);
    cudaGetSymbolAddress((void**)&bp, g_bp);
    cudaGetSymbolAddress((void**)&xt, g_xt);
    cudaGetSymbolAddress((void**)&h,  g_h);
    cudaGetSymbolAddress((void**)&ln, g_ln);
    cudaGetSymbolAddress((void**)&qb, g_qb);
    cudaGetSymbolAddress((void**)&kb, g_kb);
    cudaGetSymbolAddress((void**)&vb, g_vb);
    cudaGetSymbolAddress((void**)&ao, g_ao);
    cudaGetSymbolAddress((void**)&ff, g_ff);
    cudaGetSymbolAddress((void**)&fa, g_fa);

    gn_stats_kernel<<<32, 256>>>(x, gn_w, gn_b);
    fold_pin_kernel<<<DMODEL, 64>>>(pin_w, pin_b);
    transpose_kernel<<<dim3(128, 10), dim3(32, 8)>>>(x, xt, DMODEL, NTOK);
    transpose_kernel<<<dim3(10, 10), dim3(32, 8)>>>(pout_w, Wq, DMODEL, DMODEL);

    gemm_tc<<<dim3(32, 5), 128>>>(xt, Wp, h, bp, nullptr,
        NTOK, DMODEL, DMODEL, DMODEL, DMODEL, DMODEL, 1);

    // self-attention block
    ln_kernel<<<NTOK, 128>>>(h, ln1_w, ln1_b, ln);
    gemm_tc<<<dim3(32, 5), 128>>>(ln, q1, qb, nullptr, nullptr,
        NTOK, DMODEL, DMODEL, DMODEL, DMODEL, DMODEL, 1);
    gemm_tc<<<dim3(32, 5), 128>>>(ln, k1, kb, nullptr, nullptr,
        NTOK, DMODEL, DMODEL, DMODEL, DMODEL, DMODEL, 1);
    gemm_tc<<<dim3(32, 5), 128>>>(ln, v1, vb, nullptr, nullptr,
        NTOK, DMODEL, DMODEL, DMODEL, DMODEL, DMODEL, 1);
    attn_tc<<<dim3(NTOK / 64, HEADS), 128>>>(qb, kb, vb, ao, NTOK);
    gemm_tc<<<dim3(32, 5), 128>>>(ao, o1_w, h, o1_b, h,
        NTOK, DMODEL, DMODEL, DMODEL, DMODEL, DMODEL, 1);

    // cross-attention block
    ln_kernel<<<NTOK, 128>>>(h, ln2_w, ln2_b, ln);
    gemm_tc<<<dim3(32, 5), 128>>>(ln, q2, qb, nullptr, nullptr,
        NTOK, DMODEL, DMODEL, DMODEL, DMODEL, DMODEL, 1);
    gemm_tc<<<dim3(1, 5), 128>>>(ctx, k2, kb, nullptr, nullptr,
        CTXN, DMODEL, CTXD, CTXD, DMODEL, DMODEL, 1);
    gemm_tc<<<dim3(1, 5), 128>>>(ctx, v2, vb, nullptr, nullptr,
        CTXN, DMODEL, CTXD, CTXD, DMODEL, DMODEL, 1);
    attn_tc<<<dim3(NTOK / 64, HEADS), 128>>>(qb, kb, vb, ao, CTXN);
    gemm_tc<<<dim3(32, 5), 128>>>(ao, o2_w, h, o2_b, h,
        NTOK, DMODEL, DMODEL, DMODEL, DMODEL, DMODEL, 1);

    // GEGLU FF block
    ln_kernel<<<NTOK, 128>>>(h, ln3_w, ln3_b, ln);
    gemm_tc<<<dim3(32, 40), 128>>>(ln, ff1_w, ff, ff1_b, nullptr,
        NTOK, 2 * FFI, DMODEL, DMODEL, 2 * FFI, 2 * FFI, 1);
    geglu_kernel<<<(NTOK * FFI + 255) / 256, 256>>>(ff, fa);
    gemm_tc<<<dim3(32, 5), 128>>>(fa, ff2_w, h, ff2_b, h,
        NTOK, DMODEL, FFI, FFI, DMODEL, DMODEL, 1);

    // output projection (transposed store) + input residual
    gemm_tc<<<dim3(32, 5), 128>>>(h, Wq, out, pout_b, x,
        NTOK, DMODEL, DMODEL, DMODEL, DMODEL, 1, NTOK);
}

// round 4
// speedup vs baseline: 3.7520x; 1.5253x over previous
#include <cuda_runtime.h>
#include <cuda_bf16.h>
#include <math.h>
#include <stdint.h>

#define NTOK 4096
#define DMODEL 320
#define FFI 1280
#define HEADS 8
#define DH 40
#define CTXN 77
#define CTXD 768

// ---------------- scratch ----------------
__device__ float g_s[DMODEL];
__device__ float g_t[DMODEL];
__device__ float g_Wp[DMODEL * DMODEL];
__device__ float g_Wq[DMODEL * DMODEL];
__device__ float g_bp[DMODEL];
__device__ float g_xt[NTOK * DMODEL];
__device__ float g_h[NTOK * DMODEL];
__device__ float g_ln[NTOK * DMODEL];
__device__ float g_qb[NTOK * DMODEL];
__device__ float g_kb[NTOK * DMODEL];
__device__ float g_vb[NTOK * DMODEL];
__device__ float g_ao[NTOK * DMODEL];
__device__ float g_ff[NTOK * 2 * FFI];
__device__ float g_fa[NTOK * FFI];

// ---------------- cp.async helpers ----------------
__device__ __forceinline__ uint32_t smem_u32(const void* p) {
    return (uint32_t)__cvta_generic_to_shared(p);
}
__device__ __forceinline__ void cp16(uint32_t dst, const void* src, bool pred) {
    int sz = pred ? 16 : 0;
    asm volatile("cp.async.cg.shared.global [%0], [%1], 16, %2;" :: "r"(dst), "l"(src), "r"(sz));
}
__device__ __forceinline__ void cp_commit() { asm volatile("cp.async.commit_group;"); }
__device__ __forceinline__ void cp_wait1() { asm volatile("cp.async.wait_group 1;"); }

__device__ __forceinline__ void mma_tf32(float* d, const uint32_t* a, const uint32_t* b) {
    asm volatile(
        "mma.sync.aligned.m16n8k8.row.col.f32.tf32.tf32.f32 "
        "{%0,%1,%2,%3}, {%4,%5,%6,%7}, {%8,%9}, {%0,%1,%2,%3};"
        : "+f"(d[0]), "+f"(d[1]), "+f"(d[2]), "+f"(d[3])
        : "r"(a[0]), "r"(a[1]), "r"(a[2]), "r"(a[3]), "r"(b[0]), "r"(b[1]));
}

// ---------------- GroupNorm stats ----------------
__global__ void gn_stats_kernel(const float* __restrict__ x,
                                const float* __restrict__ gn_w,
                                const float* __restrict__ gn_b) {
    int g = blockIdx.x;
    int tid = threadIdx.x;
    const float* base = x + (size_t)g * 10 * 4096;
    float s = 0.f, ss = 0.f;
    for (int i = tid; i < 40960; i += 256) {
        float v = base[i];
        s += v; ss += v * v;
    }
    __shared__ float r1[256], r2[256];
    r1[tid] = s; r2[tid] = ss;
    __syncthreads();
    for (int off = 128; off > 0; off >>= 1) {
        if (tid < off) { r1[tid] += r1[tid + off]; r2[tid] += r2[tid + off]; }
        __syncthreads();
    }
    if (tid < 10) {
        float mu = r1[0] / 40960.f;
        float var = r2[0] / 40960.f - mu * mu;
        float inv = rsqrtf(var + 1e-6f);
        int c = g * 10 + tid;
        float w = gn_w[c];
        g_s[c] = inv * w;
        g_t[c] = gn_b[c] - mu * inv * w;
    }
}

__global__ void fold_pin_kernel(const float* __restrict__ pin_w,
                                const float* __restrict__ pin_b) {
    int o = blockIdx.x;
    int tid = threadIdx.x;
    float acc = 0.f;
    for (int c = tid; c < DMODEL; c += 64) {
        float w = pin_w[o * DMODEL + c];
        g_Wp[c * DMODEL + o] = w * g_s[c];
        acc += w * g_t[c];
    }
    __shared__ float r[64];
    r[tid] = acc;
    __syncthreads();
    for (int off = 32; off > 0; off >>= 1) {
        if (tid < off) r[tid] += r[tid + off];
        __syncthreads();
    }
    if (tid == 0) g_bp[o] = pin_b[o] + r[0];
}

// ---------------- transpose ----------------
__global__ void transpose_kernel(const float* __restrict__ in, float* __restrict__ out,
                                 int R, int Cc) {
    __shared__ float tile[32][33];
    int c0 = blockIdx.x * 32, r0 = blockIdx.y * 32;
    int tx = threadIdx.x, ty = threadIdx.y;
#pragma unroll
    for (int i = 0; i < 4; i++) {
        int r = r0 + ty + i * 8, c = c0 + tx;
        if (r < R && c < Cc) tile[ty + i * 8][tx] = in[(size_t)r * Cc + c];
    }
    __syncthreads();
#pragma unroll
    for (int i = 0; i < 4; i++) {
        int c = c0 + ty + i * 8, r = r0 + tx;
        if (c < Cc && r < R) out[(size_t)c * R + r] = tile[tx][ty + i * 8];
    }
}

// ---------------- tf32 tensor-core GEMM, 2-stage cp.async pipeline ----------------
__global__ __launch_bounds__(128) void gemm_tc(
    const float* __restrict__ A, const float* __restrict__ B, float* __restrict__ C,
    const float* __restrict__ bias, const float* __restrict__ resid,
    int M, int N, int K, int lda, int ldb, int Csm, int Csn) {
    __shared__ __align__(16) uint32_t As[2][128][20];
    __shared__ __align__(16) uint32_t Bs[2][16][72];
    int tid = threadIdx.x;
    int warp = tid >> 5, lane = tid & 31;
    int grp = lane >> 2, t4 = lane & 3;
    int m0 = blockIdx.x * 128, n0 = blockIdx.y * 64;
    int wm = (warp >> 1) * 64, wn = (warp & 1) * 32;

    float acc[4][4][4];
#pragma unroll
    for (int mi = 0; mi < 4; mi++)
#pragma unroll
        for (int ni = 0; ni < 4; ni++)
#pragma unroll
            for (int r = 0; r < 4; r++) acc[mi][ni][r] = 0.f;

    int ar = m0 + tid;
    bool apred = ar < M;
    const float* abase = A + (size_t)(apred ? ar : 0) * lda;

    auto prefetch = [&](int st, int k0) {
        uint32_t ad = smem_u32(&As[st][tid][0]);
        const float* asrc = abase + k0;
#pragma unroll
        for (int i = 0; i < 4; i++) cp16(ad + i * 16, asrc + i * 4, apred);
#pragma unroll
        for (int i = 0; i < 2; i++) {
            int f = tid + i * 128;
            int bk = f >> 4, bn = (f & 15) * 4;
            cp16(smem_u32(&Bs[st][bk][bn]), B + (size_t)(k0 + bk) * ldb + n0 + bn, true);
        }
    };

    int nK = K >> 4;
    prefetch(0, 0);
    cp_commit();
    for (int kt = 0; kt < nK; kt++) {
        if (kt + 1 < nK) prefetch((kt + 1) & 1, (kt + 1) << 4);
        cp_commit();
        cp_wait1();
        __syncthreads();
        int st = kt & 1;
#pragma unroll
        for (int kk = 0; kk < 16; kk += 8) {
            uint32_t af[4][4];
#pragma unroll
            for (int mi = 0; mi < 4; mi++) {
                int rm = wm + mi * 16;
                af[mi][0] = As[st][rm + grp][kk + t4];
                af[mi][1] = As[st][rm + grp + 8][kk + t4];
                af[mi][2] = As[st][rm + grp][kk + t4 + 4];
                af[mi][3] = As[st][rm + grp + 8][kk + t4 + 4];
            }
            uint32_t bf[4][2];
#pragma unroll
            for (int ni = 0; ni < 4; ni++) {
                int cn = wn + ni * 8 + grp;
                bf[ni][0] = Bs[st][kk + t4][cn];
                bf[ni][1] = Bs[st][kk + t4 + 4][cn];
            }
#pragma unroll
            for (int mi = 0; mi < 4; mi++)
#pragma unroll
                for (int ni = 0; ni < 4; ni++)
                    mma_tf32(acc[mi][ni], af[mi], bf[ni]);
        }
        __syncthreads();
    }
#pragma unroll
    for (int mi = 0; mi < 4; mi++) {
        int r0r = m0 + wm + mi * 16 + grp;
        int r1r = r0r + 8;
#pragma unroll
        for (int ni = 0; ni < 4; ni++) {
            int c = n0 + wn + ni * 8 + t4 * 2;
            float b0 = bias ? bias[c] : 0.f;
            float b1 = bias ? bias[c + 1] : 0.f;
            if (r0r < M) {
                size_t o0 = (size_t)r0r * Csm + (size_t)c * Csn;
                size_t o1 = o0 + Csn;
                float v0 = acc[mi][ni][0] + b0;
                float v1 = acc[mi][ni][1] + b1;
                if (resid) { v0 += resid[o0]; v1 += resid[o1]; }
                C[o0] = v0; C[o1] = v1;
            }
            if (r1r < M) {
                size_t o0 = (size_t)r1r * Csm + (size_t)c * Csn;
                size_t o1 = o0 + Csn;
                float v0 = acc[mi][ni][2] + b0;
                float v1 = acc[mi][ni][3] + b1;
                if (resid) { v0 += resid[o0]; v1 += resid[o1]; }
                C[o0] = v0; C[o1] = v1;
            }
        }
    }
}

// ---------------- LayerNorm ----------------
__global__ __launch_bounds__(128) void ln_kernel(const float* __restrict__ in,
                                                 const float* __restrict__ w,
                                                 const float* __restrict__ b,
                                                 float* __restrict__ out) {
    int m = blockIdx.x;
    int tid = threadIdx.x;
    const float* row = in + (size_t)m * DMODEL;
    float vals[3];
    float s = 0.f, ss = 0.f;
#pragma unroll
    for (int i = 0; i < 3; i++) {
        int c = tid + i * 128;
        float v = (c < DMODEL) ? row[c] : 0.f;
        vals[i] = v;
        s += v; ss += v * v;
    }
    __shared__ float r1[128], r2[128];
    r1[tid] = s; r2[tid] = ss;
    __syncthreads();
    for (int off = 64; off > 0; off >>= 1) {
        if (tid < off) { r1[tid] += r1[tid + off]; r2[tid] += r2[tid + off]; }
        __syncthreads();
    }
    float mu = r1[0] / (float)DMODEL;
    float var = r2[0] / (float)DMODEL - mu * mu;
    float rs = rsqrtf(var + 1e-5f);
#pragma unroll
    for (int i = 0; i < 3; i++) {
        int c = tid + i * 128;
        if (c < DMODEL) out[(size_t)m * DMODEL + c] = (vals[i] - mu) * rs * w[c] + b[c];
    }
}

// ---------------- tensor-core flash attention ----------------
// 128 queries x 1 head per block, 8 warps, 64-key tiles, 2-stage cp.async K/V.
// dyn smem words: Kr[2][64][44] @0, Vr[2][64][40] @5632, Ps[128][68] @10752.
#define ATTN_SMEM_BYTES (19456 * 4)
__global__ __launch_bounds__(256) void attn_tc(
    const float* __restrict__ Q, const float* __restrict__ K, const float* __restrict__ V,
    float* __restrict__ O, int n_k) {
    extern __shared__ __align__(16) uint32_t dyn[];
    uint32_t* KrS = dyn;            // [2][64][44]
    uint32_t* VrS = dyn + 5632;     // [2][64][40]
    uint32_t* PsS = dyn + 10752;    // [128][68]
#define KR(st, r, c) KrS[(st) * 2816 + (r) * 44 + (c)]
#define VR(st, r, c) VrS[(st) * 2560 + (r) * 40 + (c)]
#define PS(r, c)     PsS[(r) * 68 + (c)]

    int h = blockIdx.y;
    int m0 = blockIdx.x * 128;
    int tid = threadIdx.x;
    int warp = tid >> 5, lane = tid & 31;
    int grp = lane >> 2, t4 = lane & 3;
    int wm = warp * 16;
    int row0 = m0 + wm + grp, row1 = row0 + 8;

    const float scale = 0.15811388300841897f;
    uint32_t qf[5][4];
#pragma unroll
    for (int kt = 0; kt < 5; kt++) {
        int c = kt * 8 + t4;
        qf[kt][0] = __float_as_uint(Q[(size_t)row0 * DMODEL + h * DH + c] * scale);
        qf[kt][1] = __float_as_uint(Q[(size_t)row1 * DMODEL + h * DH + c] * scale);
        qf[kt][2] = __float_as_uint(Q[(size_t)row0 * DMODEL + h * DH + c + 4] * scale);
        qf[kt][3] = __float_as_uint(Q[(size_t)row1 * DMODEL + h * DH + c + 4] * scale);
    }

    float o[5][4];
#pragma unroll
    for (int d = 0; d < 5; d++)
#pragma unroll
        for (int r = 0; r < 4; r++) o[d][r] = 0.f;
    float m_r0 = -1e30f, m_r1 = -1e30f, l_r0 = 0.f, l_r1 = 0.f;

    auto prefetch = [&](int st, int kt0) {
        for (int t = tid; t < 640; t += 256) {
            int r = t / 10, c4 = (t - r * 10) * 4;
            bool pred = (kt0 + r) < n_k;
            size_t g = (size_t)(pred ? (kt0 + r) : 0) * DMODEL + h * DH + c4;
            cp16(smem_u32(&KR(st, r, c4)), K + g, pred);
            cp16(smem_u32(&VR(st, r, c4)), V + g, pred);
        }
    };

    int nT = (n_k + 63) >> 6;
    prefetch(0, 0);
    cp_commit();
    for (int it = 0; it < nT; it++) {
        if (it + 1 < nT) prefetch((it + 1) & 1, (it + 1) * 64);
        cp_commit();
        cp_wait1();
        __syncthreads();
        int st = it & 1;
        int kcount = min(64, n_k - it * 64);

        // S = Q @ K^T
        float s[8][4];
#pragma unroll
        for (int nt = 0; nt < 8; nt++)
#pragma unroll
            for (int r = 0; r < 4; r++) s[nt][r] = 0.f;
#pragma unroll
        for (int kt = 0; kt < 5; kt++) {
#pragma unroll
            for (int nt = 0; nt < 8; nt++) {
                uint32_t bf[2];
                bf[0] = KR(st, nt * 8 + grp, kt * 8 + t4);
                bf[1] = KR(st, nt * 8 + grp, kt * 8 + t4 + 4);
                mma_tf32(s[nt], qf[kt], bf);
            }
        }
        if (kcount < 64) {
#pragma unroll
            for (int nt = 0; nt < 8; nt++) {
                int c0 = nt * 8 + 2 * t4;
                if (c0 >= kcount)     { s[nt][0] = -1e30f; s[nt][2] = -1e30f; }
                if (c0 + 1 >= kcount) { s[nt][1] = -1e30f; s[nt][3] = -1e30f; }
            }
        }

        // online softmax
        float mx0 = m_r0, mx1 = m_r1;
#pragma unroll
        for (int nt = 0; nt < 8; nt++) {
            mx0 = fmaxf(mx0, fmaxf(s[nt][0], s[nt][1]));
            mx1 = fmaxf(mx1, fmaxf(s[nt][2], s[nt][3]));
        }
        mx0 = fmaxf(mx0, __shfl_xor_sync(0xffffffffu, mx0, 1));
        mx0 = fmaxf(mx0, __shfl_xor_sync(0xffffffffu, mx0, 2));
        mx1 = fmaxf(mx1, __shfl_xor_sync(0xffffffffu, mx1, 1));
        mx1 = fmaxf(mx1, __shfl_xor_sync(0xffffffffu, mx1, 2));
        float f0 = __expf(m_r0 - mx0), f1 = __expf(m_r1 - mx1);
        float sum0 = 0.f, sum1 = 0.f;
#pragma unroll
        for (int nt = 0; nt < 8; nt++) {
            float p0 = __expf(s[nt][0] - mx0);
            float p1 = __expf(s[nt][1] - mx0);
            float p2 = __expf(s[nt][2] - mx1);
            float p3 = __expf(s[nt][3] - mx1);
            sum0 += p0 + p1; sum1 += p2 + p3;
            int c = nt * 8 + 2 * t4;
            PS(wm + grp, c)     = __float_as_uint(p0);
            PS(wm + grp, c + 1) = __float_as_uint(p1);
            PS(wm + grp + 8, c)     = __float_as_uint(p2);
            PS(wm + grp + 8, c + 1) = __float_as_uint(p3);
        }
        sum0 += __shfl_xor_sync(0xffffffffu, sum0, 1);
        sum0 += __shfl_xor_sync(0xffffffffu, sum0, 2);
        sum1 += __shfl_xor_sync(0xffffffffu, sum1, 1);
        sum1 += __shfl_xor_sync(0xffffffffu, sum1, 2);
        l_r0 = l_r0 * f0 + sum0; m_r0 = mx0;
        l_r1 = l_r1 * f1 + sum1; m_r1 = mx1;

#pragma unroll
        for (int d = 0; d < 5; d++) {
            o[d][0] *= f0; o[d][1] *= f0;
            o[d][2] *= f1; o[d][3] *= f1;
        }
        __syncwarp();

        uint32_t pa[8][4];
#pragma unroll
        for (int ks = 0; ks < 8; ks++) {
            pa[ks][0] = PS(wm + grp, ks * 8 + t4);
            pa[ks][1] = PS(wm + grp + 8, ks * 8 + t4);
            pa[ks][2] = PS(wm + grp, ks * 8 + t4 + 4);
            pa[ks][3] = PS(wm + grp + 8, ks * 8 + t4 + 4);
        }
#pragma unroll
        for (int d = 0; d < 5; d++) {
#pragma unroll
            for (int ks = 0; ks < 8; ks++) {
                uint32_t bf[2];
                bf[0] = VR(st, ks * 8 + t4, d * 8 + grp);
                bf[1] = VR(st, ks * 8 + t4 + 4, d * 8 + grp);
                mma_tf32(o[d], pa[ks], bf);
            }
        }
        __syncthreads();
    }

    float inv0 = 1.f / l_r0, inv1 = 1.f / l_r1;
#pragma unroll
    for (int d = 0; d < 5; d++) {
        int c = h * DH + d * 8 + 2 * t4;
        O[(size_t)row0 * DMODEL + c]     = o[d][0] * inv0;
        O[(size_t)row0 * DMODEL + c + 1] = o[d][1] * inv0;
        O[(size_t)row1 * DMODEL + c]     = o[d][2] * inv1;
        O[(size_t)row1 * DMODEL + c + 1] = o[d][3] * inv1;
    }
#undef KR
#undef VR
#undef PS
}

// ---------------- GEGLU ----------------
__global__ void geglu_kernel(const float* __restrict__ ff, float* __restrict__ fa) {
    int idx = blockIdx.x * 256 + threadIdx.x;
    if (idx >= NTOK * FFI) return;
    int m = idx / FFI, j = idx % FFI;
    float a = ff[(size_t)m * 2 * FFI + j];
    float g = ff[(size_t)m * 2 * FFI + FFI + j];
    float gelu = 0.5f * g * (1.f + erff(g * 0.70710678118654752f));
    fa[idx] = a * gelu;
}

// ---------------- host launch ----------------
extern "C" void kernel_launch(void* const* d_in, const int* in_sizes, int n_in,
                              void* d_out, int out_size) {
    const float* x      = (const float*)d_in[0];
    const float* ctx    = (const float*)d_in[1];
    const float* gn_w   = (const float*)d_in[2];
    const float* gn_b   = (const float*)d_in[3];
    const float* pin_w  = (const float*)d_in[4];
    const float* pin_b  = (const float*)d_in[5];
    const float* ln1_w  = (const float*)d_in[6];
    const float* ln1_b  = (const float*)d_in[7];
    const float* q1     = (const float*)d_in[8];
    const float* k1     = (const float*)d_in[9];
    const float* v1     = (const float*)d_in[10];
    const float* o1_w   = (const float*)d_in[11];
    const float* o1_b   = (const float*)d_in[12];
    const float* ln2_w  = (const float*)d_in[13];
    const float* ln2_b  = (const float*)d_in[14];
    const float* q2     = (const float*)d_in[15];
    const float* k2     = (const float*)d_in[16];
    const float* v2     = (const float*)d_in[17];
    const float* o2_w   = (const float*)d_in[18];
    const float* o2_b   = (const float*)d_in[19];
    const float* ln3_w  = (const float*)d_in[20];
    const float* ln3_b  = (const float*)d_in[21];
    const float* ff1_w  = (const float*)d_in[22];
    const float* ff1_b  = (const float*)d_in[23];
    const float* ff2_w  = (const float*)d_in[24];
    const float* ff2_b  = (const float*)d_in[25];
    const float* pout_w = (const float*)d_in[26];
    const float* pout_b = (const float*)d_in[27];
    float* out = (float*)d_out;

    float *Wp, *Wq, *bp, *xt, *h, *ln, *qb, *kb, *vb, *ao, *ff, *fa;
    cudaGetSymbolAddress((void**)&Wp, g_Wp);
    cudaGetSymbolAddress((void**)&Wq, g_Wq);
    cudaGetSymbolAddress((void**)&bp, g_bp);
    cudaGetSymbolAddress((void**)&xt, g_xt);
    cudaGetSymbolAddress((void**)&h,  g_h);
    cudaGetSymbolAddress((void**)&ln, g_ln);
    cudaGetSymbolAddress((void**)&qb, g_qb);
    cudaGetSymbolAddress((void**)&kb, g_kb);
    cudaGetSymbolAddress((void**)&vb, g_vb);
    cudaGetSymbolAddress((void**)&ao, g_ao);
    cudaGetSymbolAddress((void**)&ff, g_ff);
    cudaGetSymbolAddress((void**)&fa, g_fa);

    static bool attr_set = false;
    if (!attr_set) {
        cudaFuncSetAttribute(attn_tc, cudaFuncAttributeMaxDynamicSharedMemorySize,
                             ATTN_SMEM_BYTES);
        attr_set = true;
    }

    gn_stats_kernel<<<32, 256>>>(x, gn_w, gn_b);
    fold_pin_kernel<<<DMODEL, 64>>>(pin_w, pin_b);
    transpose_kernel<<<dim3(128, 10), dim3(32, 8)>>>(x, xt, DMODEL, NTOK);
    transpose_kernel<<<dim3(10, 10), dim3(32, 8)>>>(pout_w, Wq, DMODEL, DMODEL);

    gemm_tc<<<dim3(32, 5), 128>>>(xt, Wp, h, bp, nullptr,
        NTOK, DMODEL, DMODEL, DMODEL, DMODEL, DMODEL, 1);

    // self-attention block
    ln_kernel<<<NTOK, 128>>>(h, ln1_w, ln1_b, ln);
    gemm_tc<<<dim3(32, 5), 128>>>(ln, q1, qb, nullptr, nullptr,
        NTOK, DMODEL, DMODEL, DMODEL, DMODEL, DMODEL, 1);
    gemm_tc<<<dim3(32, 5), 128>>>(ln, k1, kb, nullptr, nullptr,
        NTOK, DMODEL, DMODEL, DMODEL, DMODEL, DMODEL, 1);
    gemm_tc<<<dim3(32, 5), 128>>>(ln, v1, vb, nullptr, nullptr,
        NTOK, DMODEL, DMODEL, DMODEL, DMODEL, DMODEL, 1);
    attn_tc<<<dim3(NTOK / 128, HEADS), 256, ATTN_SMEM_BYTES>>>(qb, kb, vb, ao, NTOK);
    gemm_tc<<<dim3(32, 5), 128>>>(ao, o1_w, h, o1_b, h,
        NTOK, DMODEL, DMODEL, DMODEL, DMODEL, DMODEL, 1);

    // cross-attention block
    ln_kernel<<<NTOK, 128>>>(h, ln2_w, ln2_b, ln);
    gemm_tc<<<dim3(32, 5), 128>>>(ln, q2, qb, nullptr, nullptr,
        NTOK, DMODEL, DMODEL, DMODEL, DMODEL, DMODEL, 1);
    gemm_tc<<<dim3(1, 5), 128>>>(ctx, k2, kb, nullptr, nullptr,
        CTXN, DMODEL, CTXD, CTXD, DMODEL, DMODEL, 1);
    gemm_tc<<<dim3(1, 5), 128>>>(ctx, v2, vb, nullptr, nullptr,
        CTXN, DMODEL, CTXD, CTXD, DMODEL, DMODEL, 1);
    attn_tc<<<dim3(NTOK / 128, HEADS), 256, ATTN_SMEM_BYTES>>>(qb, kb, vb, ao, CTXN);
    gemm_tc<<<dim3(32, 5), 128>>>(ao, o2_w, h, o2_b, h,
        NTOK, DMODEL, DMODEL, DMODEL, DMODEL, DMODEL, 1);

    // GEGLU FF block
    ln_kernel<<<NTOK, 128>>>(h, ln3_w, ln3_b, ln);
    gemm_tc<<<dim3(32, 40), 128>>>(ln, ff1_w, ff, ff1_b, nullptr,
        NTOK, 2 * FFI, DMODEL, DMODEL, 2 * FFI, 2 * FFI, 1);
    geglu_kernel<<<(NTOK * FFI + 255) / 256, 256>>>(ff, fa);
    gemm_tc<<<dim3(32, 5), 128>>>(fa, ff2_w, h, ff2_b, h,
        NTOK, DMODEL, FFI, FFI, DMODEL, DMODEL, 1);

    // output projection (transposed store) + input residual
    gemm_tc<<<dim3(32, 5), 128>>>(h, Wq, out, pout_b, x,
        NTOK, DMODEL, DMODEL, DMODEL, DMODEL, 1, NTOK);
}

// round 5
// speedup vs baseline: 4.2866x; 1.1425x over previous
#include <cuda_runtime.h>
#include <cuda_bf16.h>
#include <math.h>
#include <stdint.h>

#define NTOK 4096
#define DMODEL 320
#define FFI 1280
#define HEADS 8
#define DH 40
#define CTXN 77
#define CTXD 768

// ---------------- scratch ----------------
__device__ float g_s[DMODEL];
__device__ float g_t[DMODEL];
__device__ float g_Wp[DMODEL * DMODEL];
__device__ float g_Wq[DMODEL * DMODEL];
__device__ float g_bp[DMODEL];
__device__ float g_xt[NTOK * DMODEL];
__device__ float g_h[NTOK * DMODEL];
__device__ float g_ln[NTOK * DMODEL];
__device__ float g_qb[NTOK * DMODEL];
__device__ float g_kb[NTOK * DMODEL];
__device__ float g_vb[NTOK * DMODEL];
__device__ float g_ao[NTOK * DMODEL];
__device__ float g_ff[NTOK * 2 * FFI];
__device__ float g_fa[NTOK * FFI];

// ---------------- cp.async helpers ----------------
__device__ __forceinline__ uint32_t smem_u32(const void* p) {
    return (uint32_t)__cvta_generic_to_shared(p);
}
__device__ __forceinline__ void cp16(uint32_t dst, const void* src, bool pred) {
    int sz = pred ? 16 : 0;
    asm volatile("cp.async.cg.shared.global [%0], [%1], 16, %2;" :: "r"(dst), "l"(src), "r"(sz));
}
__device__ __forceinline__ void cp_commit() { asm volatile("cp.async.commit_group;"); }
__device__ __forceinline__ void cp_wait1() { asm volatile("cp.async.wait_group 1;"); }

__device__ __forceinline__ void mma_tf32(float* d, const uint32_t* a, const uint32_t* b) {
    asm volatile(
        "mma.sync.aligned.m16n8k8.row.col.f32.tf32.tf32.f32 "
        "{%0,%1,%2,%3}, {%4,%5,%6,%7}, {%8,%9}, {%0,%1,%2,%3};"
        : "+f"(d[0]), "+f"(d[1]), "+f"(d[2]), "+f"(d[3])
        : "r"(a[0]), "r"(a[1]), "r"(a[2]), "r"(a[3]), "r"(b[0]), "r"(b[1]));
}

// ---------------- GroupNorm stats ----------------
__global__ void gn_stats_kernel(const float* __restrict__ x,
                                const float* __restrict__ gn_w,
                                const float* __restrict__ gn_b) {
    int g = blockIdx.x;
    int tid = threadIdx.x;
    const float* base = x + (size_t)g * 10 * 4096;
    float s = 0.f, ss = 0.f;
    for (int i = tid; i < 40960; i += 256) {
        float v = base[i];
        s += v; ss += v * v;
    }
    __shared__ float r1[256], r2[256];
    r1[tid] = s; r2[tid] = ss;
    __syncthreads();
    for (int off = 128; off > 0; off >>= 1) {
        if (tid < off) { r1[tid] += r1[tid + off]; r2[tid] += r2[tid + off]; }
        __syncthreads();
    }
    if (tid < 10) {
        float mu = r1[0] / 40960.f;
        float var = r2[0] / 40960.f - mu * mu;
        float inv = rsqrtf(var + 1e-6f);
        int c = g * 10 + tid;
        float w = gn_w[c];
        g_s[c] = inv * w;
        g_t[c] = gn_b[c] - mu * inv * w;
    }
}

__global__ void fold_pin_kernel(const float* __restrict__ pin_w,
                                const float* __restrict__ pin_b) {
    int o = blockIdx.x;
    int tid = threadIdx.x;
    float acc = 0.f;
    for (int c = tid; c < DMODEL; c += 64) {
        float w = pin_w[o * DMODEL + c];
        g_Wp[c * DMODEL + o] = w * g_s[c];
        acc += w * g_t[c];
    }
    __shared__ float r[64];
    r[tid] = acc;
    __syncthreads();
    for (int off = 32; off > 0; off >>= 1) {
        if (tid < off) r[tid] += r[tid + off];
        __syncthreads();
    }
    if (tid == 0) g_bp[o] = pin_b[o] + r[0];
}

// ---------------- transpose ----------------
__global__ void transpose_kernel(const float* __restrict__ in, float* __restrict__ out,
                                 int R, int Cc) {
    __shared__ float tile[32][33];
    int c0 = blockIdx.x * 32, r0 = blockIdx.y * 32;
    int tx = threadIdx.x, ty = threadIdx.y;
#pragma unroll
    for (int i = 0; i < 4; i++) {
        int r = r0 + ty + i * 8, c = c0 + tx;
        if (r < R && c < Cc) tile[ty + i * 8][tx] = in[(size_t)r * Cc + c];
    }
    __syncthreads();
#pragma unroll
    for (int i = 0; i < 4; i++) {
        int c = c0 + ty + i * 8, r = r0 + tx;
        if (c < Cc && r < R) out[(size_t)c * R + r] = tile[tx][ty + i * 8];
    }
}

// ---------------- tf32 tensor-core GEMM ----------------
// BM=128, BN=64, BK=16, 256 threads / 8 warps (4m x 2n), warp tile 32x32.
__global__ __launch_bounds__(256) void gemm_tc(
    const float* __restrict__ A, const float* __restrict__ B, float* __restrict__ C,
    const float* __restrict__ bias, const float* __restrict__ resid,
    int M, int N, int K, int lda, int ldb, int Csm, int Csn) {
    __shared__ __align__(16) uint32_t As[2][128][20];
    __shared__ __align__(16) uint32_t Bs[2][16][72];
    int tid = threadIdx.x;
    int warp = tid >> 5, lane = tid & 31;
    int grp = lane >> 2, t4 = lane & 3;
    int m0 = blockIdx.x * 128, n0 = blockIdx.y * 64;
    int wm = (warp >> 1) * 32, wn = (warp & 1) * 32;

    float acc[2][4][4];
#pragma unroll
    for (int mi = 0; mi < 2; mi++)
#pragma unroll
        for (int ni = 0; ni < 4; ni++)
#pragma unroll
            for (int r = 0; r < 4; r++) acc[mi][ni][r] = 0.f;

    // A: 128 rows x 16k = 512 float4, 2 per thread; B: 256 float4, 1 per thread
    int ra0 = tid >> 2, ka0 = (tid & 3) * 4;
    int ra1 = ra0 + 64;
    bool ap0 = (m0 + ra0) < M, ap1 = (m0 + ra1) < M;
    const float* a0 = A + (size_t)(ap0 ? (m0 + ra0) : 0) * lda + ka0;
    const float* a1 = A + (size_t)(ap1 ? (m0 + ra1) : 0) * lda + ka0;
    int bk0 = tid >> 4, bn0 = (tid & 15) * 4;
    const float* bsrc = B + (size_t)bk0 * ldb + n0 + bn0;

    auto prefetch = [&](int st, int k0) {
        cp16(smem_u32(&As[st][ra0][ka0]), a0 + k0, ap0);
        cp16(smem_u32(&As[st][ra1][ka0]), a1 + k0, ap1);
        cp16(smem_u32(&Bs[st][bk0][bn0]), bsrc + (size_t)k0 * ldb, true);
    };

    int nK = K >> 4;
    prefetch(0, 0);
    cp_commit();
    for (int kt = 0; kt < nK; kt++) {
        if (kt + 1 < nK) prefetch((kt + 1) & 1, (kt + 1) << 4);
        cp_commit();
        cp_wait1();
        __syncthreads();
        int st = kt & 1;
#pragma unroll
        for (int kk = 0; kk < 16; kk += 8) {
            uint32_t af[2][4];
#pragma unroll
            for (int mi = 0; mi < 2; mi++) {
                int rm = wm + mi * 16;
                af[mi][0] = As[st][rm + grp][kk + t4];
                af[mi][1] = As[st][rm + grp + 8][kk + t4];
                af[mi][2] = As[st][rm + grp][kk + t4 + 4];
                af[mi][3] = As[st][rm + grp + 8][kk + t4 + 4];
            }
            uint32_t bf[4][2];
#pragma unroll
            for (int ni = 0; ni < 4; ni++) {
                int cn = wn + ni * 8 + grp;
                bf[ni][0] = Bs[st][kk + t4][cn];
                bf[ni][1] = Bs[st][kk + t4 + 4][cn];
            }
#pragma unroll
            for (int mi = 0; mi < 2; mi++)
#pragma unroll
                for (int ni = 0; ni < 4; ni++)
                    mma_tf32(acc[mi][ni], af[mi], bf[ni]);
        }
        __syncthreads();
    }
#pragma unroll
    for (int mi = 0; mi < 2; mi++) {
        int r0r = m0 + wm + mi * 16 + grp;
        int r1r = r0r + 8;
#pragma unroll
        for (int ni = 0; ni < 4; ni++) {
            int c = n0 + wn + ni * 8 + t4 * 2;
            float b0 = bias ? bias[c] : 0.f;
            float b1 = bias ? bias[c + 1] : 0.f;
            if (r0r < M) {
                size_t o0 = (size_t)r0r * Csm + (size_t)c * Csn;
                size_t o1 = o0 + Csn;
                float v0 = acc[mi][ni][0] + b0;
                float v1 = acc[mi][ni][1] + b1;
                if (resid) { v0 += resid[o0]; v1 += resid[o1]; }
                C[o0] = v0; C[o1] = v1;
            }
            if (r1r < M) {
                size_t o0 = (size_t)r1r * Csm + (size_t)c * Csn;
                size_t o1 = o0 + Csn;
                float v0 = acc[mi][ni][2] + b0;
                float v1 = acc[mi][ni][3] + b1;
                if (resid) { v0 += resid[o0]; v1 += resid[o1]; }
                C[o0] = v0; C[o1] = v1;
            }
        }
    }
}

// ---------------- LayerNorm ----------------
__global__ __launch_bounds__(128) void ln_kernel(const float* __restrict__ in,
                                                 const float* __restrict__ w,
                                                 const float* __restrict__ b,
                                                 float* __restrict__ out) {
    int m = blockIdx.x;
    int tid = threadIdx.x;
    const float* row = in + (size_t)m * DMODEL;
    float vals[3];
    float s = 0.f, ss = 0.f;
#pragma unroll
    for (int i = 0; i < 3; i++) {
        int c = tid + i * 128;
        float v = (c < DMODEL) ? row[c] : 0.f;
        vals[i] = v;
        s += v; ss += v * v;
    }
    __shared__ float r1[128], r2[128];
    r1[tid] = s; r2[tid] = ss;
    __syncthreads();
    for (int off = 64; off > 0; off >>= 1) {
        if (tid < off) { r1[tid] += r1[tid + off]; r2[tid] += r2[tid + off]; }
        __syncthreads();
    }
    float mu = r1[0] / (float)DMODEL;
    float var = r2[0] / (float)DMODEL - mu * mu;
    float rs = rsqrtf(var + 1e-5f);
#pragma unroll
    for (int i = 0; i < 3; i++) {
        int c = tid + i * 128;
        if (c < DMODEL) out[(size_t)m * DMODEL + c] = (vals[i] - mu) * rs * w[c] + b[c];
    }
}

// ---------------- tensor-core flash attention ----------------
#define ATTN_SMEM_BYTES (19456 * 4)
__global__ __launch_bounds__(256) void attn_tc(
    const float* __restrict__ Q, const float* __restrict__ K, const float* __restrict__ V,
    float* __restrict__ O, int n_k) {
    extern __shared__ __align__(16) uint32_t dyn[];
    uint32_t* KrS = dyn;            // [2][64][44]
    uint32_t* VrS = dyn + 5632;     // [2][64][40]
    uint32_t* PsS = dyn + 10752;    // [128][68]
#define KR(st, r, c) KrS[(st) * 2816 + (r) * 44 + (c)]
#define VR(st, r, c) VrS[(st) * 2560 + (r) * 40 + (c)]
#define PS(r, c)     PsS[(r) * 68 + (c)]

    int h = blockIdx.y;
    int m0 = blockIdx.x * 128;
    int tid = threadIdx.x;
    int warp = tid >> 5, lane = tid & 31;
    int grp = lane >> 2, t4 = lane & 3;
    int wm = warp * 16;
    int row0 = m0 + wm + grp, row1 = row0 + 8;

    const float scale = 0.15811388300841897f;
    uint32_t qf[5][4];
#pragma unroll
    for (int kt = 0; kt < 5; kt++) {
        int c = kt * 8 + t4;
        qf[kt][0] = __float_as_uint(Q[(size_t)row0 * DMODEL + h * DH + c] * scale);
        qf[kt][1] = __float_as_uint(Q[(size_t)row1 * DMODEL + h * DH + c] * scale);
        qf[kt][2] = __float_as_uint(Q[(size_t)row0 * DMODEL + h * DH + c + 4] * scale);
        qf[kt][3] = __float_as_uint(Q[(size_t)row1 * DMODEL + h * DH + c + 4] * scale);
    }

    float o[5][4];
#pragma unroll
    for (int d = 0; d < 5; d++)
#pragma unroll
        for (int r = 0; r < 4; r++) o[d][r] = 0.f;
    float m_r0 = -1e30f, m_r1 = -1e30f, l_r0 = 0.f, l_r1 = 0.f;

    auto prefetch = [&](int st, int kt0) {
        for (int t = tid; t < 640; t += 256) {
            int r = t / 10, c4 = (t - r * 10) * 4;
            bool pred = (kt0 + r) < n_k;
            size_t g = (size_t)(pred ? (kt0 + r) : 0) * DMODEL + h * DH + c4;
            cp16(smem_u32(&KR(st, r, c4)), K + g, pred);
            cp16(smem_u32(&VR(st, r, c4)), V + g, pred);
        }
    };

    int nT = (n_k + 63) >> 6;
    prefetch(0, 0);
    cp_commit();
    for (int it = 0; it < nT; it++) {
        if (it + 1 < nT) prefetch((it + 1) & 1, (it + 1) * 64);
        cp_commit();
        cp_wait1();
        __syncthreads();
        int st = it & 1;
        int kcount = min(64, n_k - it * 64);

        float s[8][4];
#pragma unroll
        for (int nt = 0; nt < 8; nt++)
#pragma unroll
            for (int r = 0; r < 4; r++) s[nt][r] = 0.f;
#pragma unroll
        for (int kt = 0; kt < 5; kt++) {
#pragma unroll
            for (int nt = 0; nt < 8; nt++) {
                uint32_t bf[2];
                bf[0] = KR(st, nt * 8 + grp, kt * 8 + t4);
                bf[1] = KR(st, nt * 8 + grp, kt * 8 + t4 + 4);
                mma_tf32(s[nt], qf[kt], bf);
            }
        }
        if (kcount < 64) {
#pragma unroll
            for (int nt = 0; nt < 8; nt++) {
                int c0 = nt * 8 + 2 * t4;
                if (c0 >= kcount)     { s[nt][0] = -1e30f; s[nt][2] = -1e30f; }
                if (c0 + 1 >= kcount) { s[nt][1] = -1e30f; s[nt][3] = -1e30f; }
            }
        }

        float mx0 = m_r0, mx1 = m_r1;
#pragma unroll
        for (int nt = 0; nt < 8; nt++) {
            mx0 = fmaxf(mx0, fmaxf(s[nt][0], s[nt][1]));
            mx1 = fmaxf(mx1, fmaxf(s[nt][2], s[nt][3]));
        }
        mx0 = fmaxf(mx0, __shfl_xor_sync(0xffffffffu, mx0, 1));
        mx0 = fmaxf(mx0, __shfl_xor_sync(0xffffffffu, mx0, 2));
        mx1 = fmaxf(mx1, __shfl_xor_sync(0xffffffffu, mx1, 1));
        mx1 = fmaxf(mx1, __shfl_xor_sync(0xffffffffu, mx1, 2));
        float f0 = __expf(m_r0 - mx0), f1 = __expf(m_r1 - mx1);
        float sum0 = 0.f, sum1 = 0.f;
#pragma unroll
        for (int nt = 0; nt < 8; nt++) {
            float p0 = __expf(s[nt][0] - mx0);
            float p1 = __expf(s[nt][1] - mx0);
            float p2 = __expf(s[nt][2] - mx1);
            float p3 = __expf(s[nt][3] - mx1);
            sum0 += p0 + p1; sum1 += p2 + p3;
            int c = nt * 8 + 2 * t4;
            PS(wm + grp, c)     = __float_as_uint(p0);
            PS(wm + grp, c + 1) = __float_as_uint(p1);
            PS(wm + grp + 8, c)     = __float_as_uint(p2);
            PS(wm + grp + 8, c + 1) = __float_as_uint(p3);
        }
        sum0 += __shfl_xor_sync(0xffffffffu, sum0, 1);
        sum0 += __shfl_xor_sync(0xffffffffu, sum0, 2);
        sum1 += __shfl_xor_sync(0xffffffffu, sum1, 1);
        sum1 += __shfl_xor_sync(0xffffffffu, sum1, 2);
        l_r0 = l_r0 * f0 + sum0; m_r0 = mx0;
        l_r1 = l_r1 * f1 + sum1; m_r1 = mx1;

#pragma unroll
        for (int d = 0; d < 5; d++) {
            o[d][0] *= f0; o[d][1] *= f0;
            o[d][2] *= f1; o[d][3] *= f1;
        }
        __syncwarp();

        uint32_t pa[8][4];
#pragma unroll
        for (int ks = 0; ks < 8; ks++) {
            pa[ks][0] = PS(wm + grp, ks * 8 + t4);
            pa[ks][1] = PS(wm + grp + 8, ks * 8 + t4);
            pa[ks][2] = PS(wm + grp, ks * 8 + t4 + 4);
            pa[ks][3] = PS(wm + grp + 8, ks * 8 + t4 + 4);
        }
#pragma unroll
        for (int d = 0; d < 5; d++) {
#pragma unroll
            for (int ks = 0; ks < 8; ks++) {
                uint32_t bf[2];
                bf[0] = VR(st, ks * 8 + t4, d * 8 + grp);
                bf[1] = VR(st, ks * 8 + t4 + 4, d * 8 + grp);
                mma_tf32(o[d], pa[ks], bf);
            }
        }
        __syncthreads();
    }

    float inv0 = 1.f / l_r0, inv1 = 1.f / l_r1;
#pragma unroll
    for (int d = 0; d < 5; d++) {
        int c = h * DH + d * 8 + 2 * t4;
        O[(size_t)row0 * DMODEL + c]     = o[d][0] * inv0;
        O[(size_t)row0 * DMODEL + c + 1] = o[d][1] * inv0;
        O[(size_t)row1 * DMODEL + c]     = o[d][2] * inv1;
        O[(size_t)row1 * DMODEL + c + 1] = o[d][3] * inv1;
    }
#undef KR
#undef VR
#undef PS
}

// ---------------- GEGLU (float4) ----------------
__global__ void geglu_kernel(const float* __restrict__ ff, float* __restrict__ fa) {
    int idx = blockIdx.x * 256 + threadIdx.x;
    if (idx >= NTOK * FFI / 4) return;
    int m = idx / (FFI / 4), j4 = (idx - m * (FFI / 4)) * 4;
    float4 a = *(const float4*)(ff + (size_t)m * 2 * FFI + j4);
    float4 g = *(const float4*)(ff + (size_t)m * 2 * FFI + FFI + j4);
    float4 r;
    r.x = a.x * 0.5f * g.x * (1.f + erff(g.x * 0.70710678118654752f));
    r.y = a.y * 0.5f * g.y * (1.f + erff(g.y * 0.70710678118654752f));
    r.z = a.z * 0.5f * g.z * (1.f + erff(g.z * 0.70710678118654752f));
    r.w = a.w * 0.5f * g.w * (1.f + erff(g.w * 0.70710678118654752f));
    *(float4*)(fa + (size_t)m * FFI + j4) = r;
}

// ---------------- host launch ----------------
extern "C" void kernel_launch(void* const* d_in, const int* in_sizes, int n_in,
                              void* d_out, int out_size) {
    const float* x      = (const float*)d_in[0];
    const float* ctx    = (const float*)d_in[1];
    const float* gn_w   = (const float*)d_in[2];
    const float* gn_b   = (const float*)d_in[3];
    const float* pin_w  = (const float*)d_in[4];
    const float* pin_b  = (const float*)d_in[5];
    const float* ln1_w  = (const float*)d_in[6];
    const float* ln1_b  = (const float*)d_in[7];
    const float* q1     = (const float*)d_in[8];
    const float* k1     = (const float*)d_in[9];
    const float* v1     = (const float*)d_in[10];
    const float* o1_w   = (const float*)d_in[11];
    const float* o1_b   = (const float*)d_in[12];
    const float* ln2_w  = (const float*)d_in[13];
    const float* ln2_b  = (const float*)d_in[14];
    const float* q2     = (const float*)d_in[15];
    const float* k2     = (const float*)d_in[16];
    const float* v2     = (const float*)d_in[17];
    const float* o2_w   = (const float*)d_in[18];
    const float* o2_b   = (const float*)d_in[19];
    const float* ln3_w  = (const float*)d_in[20];
    const float* ln3_b  = (const float*)d_in[21];
    const float* ff1_w  = (const float*)d_in[22];
    const float* ff1_b  = (const float*)d_in[23];
    const float* ff2_w  = (const float*)d_in[24];
    const float* ff2_b  = (const float*)d_in[25];
    const float* pout_w = (const float*)d_in[26];
    const float* pout_b = (const float*)d_in[27];
    float* out = (float*)d_out;

    float *Wp, *Wq, *bp, *xt, *h, *ln, *qb, *kb, *vb, *ao, *ff, *fa;
    cudaGetSymbolAddress((void**)&Wp, g_Wp);
    cudaGetSymbolAddress((void**)&Wq, g_Wq);
    cudaGetSymbolAddress((void**)&bp, g_bp);
    cudaGetSymbolAddress((void**)&xt, g_xt);
    cudaGetSymbolAddress((void**)&h,  g_h);
    cudaGetSymbolAddress((void**)&ln, g_ln);
    cudaGetSymbolAddress((void**)&qb, g_qb);
    cudaGetSymbolAddress((void**)&kb, g_kb);
    cudaGetSymbolAddress((void**)&vb, g_vb);
    cudaGetSymbolAddress((void**)&ao, g_ao);
    cudaGetSymbolAddress((void**)&ff, g_ff);
    cudaGetSymbolAddress((void**)&fa, g_fa);

    static bool attr_set = false;
    if (!attr_set) {
        cudaFuncSetAttribute(attn_tc, cudaFuncAttributeMaxDynamicSharedMemorySize,
                             ATTN_SMEM_BYTES);
        attr_set = true;
    }

    gn_stats_kernel<<<32, 256>>>(x, gn_w, gn_b);
    fold_pin_kernel<<<DMODEL, 64>>>(pin_w, pin_b);
    transpose_kernel<<<dim3(128, 10), dim3(32, 8)>>>(x, xt, DMODEL, NTOK);
    transpose_kernel<<<dim3(10, 10), dim3(32, 8)>>>(pout_w, Wq, DMODEL, DMODEL);

    gemm_tc<<<dim3(32, 5), 256>>>(xt, Wp, h, bp, nullptr,
        NTOK, DMODEL, DMODEL, DMODEL, DMODEL, DMODEL, 1);

    // self-attention block
    ln_kernel<<<NTOK, 128>>>(h, ln1_w, ln1_b, ln);
    gemm_tc<<<dim3(32, 5), 256>>>(ln, q1, qb, nullptr, nullptr,
        NTOK, DMODEL, DMODEL, DMODEL, DMODEL, DMODEL, 1);
    gemm_tc<<<dim3(32, 5), 256>>>(ln, k1, kb, nullptr, nullptr,
        NTOK, DMODEL, DMODEL, DMODEL, DMODEL, DMODEL, 1);
    gemm_tc<<<dim3(32, 5), 256>>>(ln, v1, vb, nullptr, nullptr,
        NTOK, DMODEL, DMODEL, DMODEL, DMODEL, DMODEL, 1);
    attn_tc<<<dim3(NTOK / 128, HEADS), 256, ATTN_SMEM_BYTES>>>(qb, kb, vb, ao, NTOK);
    gemm_tc<<<dim3(32, 5), 256>>>(ao, o1_w, h, o1_b, h,
        NTOK, DMODEL, DMODEL, DMODEL, DMODEL, DMODEL, 1);

    // cross-attention block
    ln_kernel<<<NTOK, 128>>>(h, ln2_w, ln2_b, ln);
    gemm_tc<<<dim3(32, 5), 256>>>(ln, q2, qb, nullptr, nullptr,
        NTOK, DMODEL, DMODEL, DMODEL, DMODEL, DMODEL, 1);
    gemm_tc<<<dim3(1, 5), 256>>>(ctx, k2, kb, nullptr, nullptr,
        CTXN, DMODEL, CTXD, CTXD, DMODEL, DMODEL, 1);
    gemm_tc<<<dim3(1, 5), 256>>>(ctx, v2, vb, nullptr, nullptr,
        CTXN, DMODEL, CTXD, CTXD, DMODEL, DMODEL, 1);
    attn_tc<<<dim3(NTOK / 128, HEADS), 256, ATTN_SMEM_BYTES>>>(qb, kb, vb, ao, CTXN);
    gemm_tc<<<dim3(32, 5), 256>>>(ao, o2_w, h, o2_b, h,
        NTOK, DMODEL, DMODEL, DMODEL, DMODEL, DMODEL, 1);

    // GEGLU FF block
    ln_kernel<<<NTOK, 128>>>(h, ln3_w, ln3_b, ln);
    gemm_tc<<<dim3(32, 40), 256>>>(ln, ff1_w, ff, ff1_b, nullptr,
        NTOK, 2 * FFI, DMODEL, DMODEL, 2 * FFI, 2 * FFI, 1);
    geglu_kernel<<<(NTOK * FFI / 4 + 255) / 256, 256>>>(ff, fa);
    gemm_tc<<<dim3(32, 5), 256>>>(fa, ff2_w, h, ff2_b, h,
        NTOK, DMODEL, FFI, FFI, DMODEL, DMODEL, 1);

    // output projection (transposed store) + input residual
    gemm_tc<<<dim3(32, 5), 256>>>(h, Wq, out, pout_b, x,
        NTOK, DMODEL, DMODEL, DMODEL, DMODEL, 1, NTOK);
}

// round 7
// speedup vs baseline: 4.8660x; 1.1351x over previous
#include <cuda_runtime.h>
#include <cuda_bf16.h>
#include <math.h>
#include <stdint.h>

#define NTOK 4096
#define DMODEL 320
#define FFI 1280
#define HEADS 8
#define DH 40
#define CTXN 77
#define CTXD 768

// ---------------- scratch ----------------
__device__ float g_s[DMODEL];
__device__ float g_t[DMODEL];
__device__ float g_Wp[DMODEL * DMODEL];       // folded pin weight [c_in][c_out]
__device__ float g_Wq[DMODEL * DMODEL];       // pout_w transposed [in][out]
__device__ float g_bp[DMODEL];
__device__ float g_xt[NTOK * DMODEL];
__device__ float g_h[NTOK * DMODEL];
__device__ float g_ln[NTOK * DMODEL];
__device__ float g_qb[NTOK * DMODEL];
__device__ float g_qkv[NTOK * 3 * DMODEL];    // packed q|k|v, stride 960
__device__ float g_kv2[CTXN * 2 * DMODEL];    // packed k|v cross, stride 640
__device__ float g_ao[NTOK * DMODEL];
__device__ float g_fa[NTOK * FFI];
__device__ float g_wqkv[DMODEL * 3 * DMODEL]; // [320][960]
__device__ float g_wkv2[CTXD * 2 * DMODEL];   // [768][640]
__device__ float g_wff1[DMODEL * 2 * FFI];    // interleaved (a,g) columns
__device__ float g_bff1[2 * FFI];

// ---------------- helpers ----------------
__device__ __forceinline__ uint32_t smem_u32(const void* p) {
    return (uint32_t)__cvta_generic_to_shared(p);
}
__device__ __forceinline__ void cp16(uint32_t dst, const void* src, bool pred) {
    int sz = pred ? 16 : 0;
    asm volatile("cp.async.cg.shared.global [%0], [%1], 16, %2;" :: "r"(dst), "l"(src), "r"(sz));
}
__device__ __forceinline__ void cp_commit() { asm volatile("cp.async.commit_group;"); }
__device__ __forceinline__ void cp_wait1() { asm volatile("cp.async.wait_group 1;"); }

__device__ __forceinline__ void mma_tf32(float* d, const uint32_t* a, const uint32_t* b) {
    asm volatile(
        "mma.sync.aligned.m16n8k8.row.col.f32.tf32.tf32.f32 "
        "{%0,%1,%2,%3}, {%4,%5,%6,%7}, {%8,%9}, {%0,%1,%2,%3};"
        : "+f"(d[0]), "+f"(d[1]), "+f"(d[2]), "+f"(d[3])
        : "r"(a[0]), "r"(a[1]), "r"(a[2]), "r"(a[3]), "r"(b[0]), "r"(b[1]));
}
__device__ __forceinline__ float gelu_f(float g) {
    return 0.5f * g * (1.f + erff(g * 0.70710678118654752f));
}

// ---------------- GroupNorm stats ----------------
__global__ void gn_stats_kernel(const float* __restrict__ x,
                                const float* __restrict__ gn_w,
                                const float* __restrict__ gn_b) {
    int g = blockIdx.x;
    int tid = threadIdx.x;
    const float* base = x + (size_t)g * 10 * 4096;
    float s = 0.f, ss = 0.f;
    for (int i = tid; i < 40960; i += 256) {
        float v = base[i];
        s += v; ss += v * v;
    }
    __shared__ float r1[256], r2[256];
    r1[tid] = s; r2[tid] = ss;
    __syncthreads();
    for (int off = 128; off > 0; off >>= 1) {
        if (tid < off) { r1[tid] += r1[tid + off]; r2[tid] += r2[tid + off]; }
        __syncthreads();
    }
    if (tid < 10) {
        float mu = r1[0] / 40960.f;
        float var = r2[0] / 40960.f - mu * mu;
        float inv = rsqrtf(var + 1e-6f);
        int c = g * 10 + tid;
        float w = gn_w[c];
        g_s[c] = inv * w;
        g_t[c] = gn_b[c] - mu * inv * w;
    }
}

__global__ void fold_pin_kernel(const float* __restrict__ pin_w,
                                const float* __restrict__ pin_b) {
    int o = blockIdx.x;
    int tid = threadIdx.x;
    float acc = 0.f;
    for (int c = tid; c < DMODEL; c += 64) {
        float w = pin_w[o * DMODEL + c];
        g_Wp[c * DMODEL + o] = w * g_s[c];
        acc += w * g_t[c];
    }
    __shared__ float r[64];
    r[tid] = acc;
    __syncthreads();
    for (int off = 32; off > 0; off >>= 1) {
        if (tid < off) r[tid] += r[tid + off];
        __syncthreads();
    }
    if (tid == 0) g_bp[o] = pin_b[o] + r[0];
}

// ---------------- transpose ----------------
__global__ void transpose_kernel(const float* __restrict__ in, float* __restrict__ out,
                                 int R, int Cc) {
    __shared__ float tile[32][33];
    int c0 = blockIdx.x * 32, r0 = blockIdx.y * 32;
    int tx = threadIdx.x, ty = threadIdx.y;
#pragma unroll
    for (int i = 0; i < 4; i++) {
        int r = r0 + ty + i * 8, c = c0 + tx;
        if (r < R && c < Cc) tile[ty + i * 8][tx] = in[(size_t)r * Cc + c];
    }
    __syncthreads();
#pragma unroll
    for (int i = 0; i < 4; i++) {
        int c = c0 + ty + i * 8, r = r0 + tx;
        if (c < Cc && r < R) out[(size_t)c * R + r] = tile[tx][ty + i * 8];
    }
}

// ---------------- weight packing ----------------
// concat3: o[k][3N] = [a|b|c] per k row
__global__ void concat3_kernel(const float* __restrict__ a, const float* __restrict__ b,
                               const float* __restrict__ c, float* __restrict__ o,
                               int K, int N) {
    int idx = blockIdx.x * 256 + threadIdx.x;
    if (idx >= K * N) return;
    int k = idx / N, n = idx - k * N;
    size_t ob = (size_t)k * 3 * N + n;
    o[ob] = a[idx]; o[ob + N] = b[idx]; o[ob + 2 * N] = c[idx];
}
__global__ void concat2_kernel(const float* __restrict__ a, const float* __restrict__ b,
                               float* __restrict__ o, int K, int N) {
    int idx = blockIdx.x * 256 + threadIdx.x;
    if (idx >= K * N) return;
    int k = idx / N, n = idx - k * N;
    size_t ob = (size_t)k * 2 * N + n;
    o[ob] = a[idx]; o[ob + N] = b[idx];
}
// interleave ff1 columns: out[k][2j] = w[k][j], out[k][2j+1] = w[k][FFI+j]
__global__ void ffperm_kernel(const float* __restrict__ w, const float* __restrict__ bias,
                              float* __restrict__ wo, float* __restrict__ bo) {
    int idx = blockIdx.x * 256 + threadIdx.x;
    if (idx >= DMODEL * FFI) return;
    int k = idx / FFI, j = idx - k * FFI;
    size_t rb = (size_t)k * 2 * FFI;
    wo[rb + 2 * j]     = w[rb + j];
    wo[rb + 2 * j + 1] = w[rb + FFI + j];
    if (k == 0) {
        bo[2 * j] = bias[j];
        bo[2 * j + 1] = bias[FFI + j];
    }
}

// ---------------- tf32 tensor-core GEMM ----------------
// BM=128, BN=64, BK=16, 256 threads / 8 warps, warp tile 32x32.
// geglu: out col pair (c,c+1)=(a,g) -> C[m][c/2] = a*gelu(g)  (Csn must be 1)
__global__ __launch_bounds__(256) void gemm_tc(
    const float* __restrict__ A, const float* __restrict__ B, float* __restrict__ C,
    const float* __restrict__ bias, const float* __restrict__ resid,
    int M, int N, int K, int lda, int ldb, int Csm, int Csn, int geglu) {
    __shared__ __align__(16) uint32_t As[2][128][20];
    __shared__ __align__(16) uint32_t Bs[2][16][72];
    int tid = threadIdx.x;
    int warp = tid >> 5, lane = tid & 31;
    int grp = lane >> 2, t4 = lane & 3;
    int m0 = blockIdx.x * 128, n0 = blockIdx.y * 64;
    int wm = (warp >> 1) * 32, wn = (warp & 1) * 32;

    float acc[2][4][4];
#pragma unroll
    for (int mi = 0; mi < 2; mi++)
#pragma unroll
        for (int ni = 0; ni < 4; ni++)
#pragma unroll
            for (int r = 0; r < 4; r++) acc[mi][ni][r] = 0.f;

    int ra0 = tid >> 2, ka0 = (tid & 3) * 4;
    int ra1 = ra0 + 64;
    bool ap0 = (m0 + ra0) < M, ap1 = (m0 + ra1) < M;
    const float* a0 = A + (size_t)(ap0 ? (m0 + ra0) : 0) * lda + ka0;
    const float* a1 = A + (size_t)(ap1 ? (m0 + ra1) : 0) * lda + ka0;
    int bk0 = tid >> 4, bn0 = (tid & 15) * 4;
    const float* bsrc = B + (size_t)bk0 * ldb + n0 + bn0;

    auto prefetch = [&](int st, int k0) {
        cp16(smem_u32(&As[st][ra0][ka0]), a0 + k0, ap0);
        cp16(smem_u32(&As[st][ra1][ka0]), a1 + k0, ap1);
        cp16(smem_u32(&Bs[st][bk0][bn0]), bsrc + (size_t)k0 * ldb, true);
    };

    int nK = K >> 4;
    prefetch(0, 0);
    cp_commit();
    for (int kt = 0; kt < nK; kt++) {
        if (kt + 1 < nK) prefetch((kt + 1) & 1, (kt + 1) << 4);
        cp_commit();
        cp_wait1();
        __syncthreads();
        int st = kt & 1;
#pragma unroll
        for (int kk = 0; kk < 16; kk += 8) {
            uint32_t af[2][4];
#pragma unroll
            for (int mi = 0; mi < 2; mi++) {
                int rm = wm + mi * 16;
                af[mi][0] = As[st][rm + grp][kk + t4];
                af[mi][1] = As[st][rm + grp + 8][kk + t4];
                af[mi][2] = As[st][rm + grp][kk + t4 + 4];
                af[mi][3] = As[st][rm + grp + 8][kk + t4 + 4];
            }
            uint32_t bf[4][2];
#pragma unroll
            for (int ni = 0; ni < 4; ni++) {
                int cn = wn + ni * 8 + grp;
                bf[ni][0] = Bs[st][kk + t4][cn];
                bf[ni][1] = Bs[st][kk + t4 + 4][cn];
            }
#pragma unroll
            for (int mi = 0; mi < 2; mi++)
#pragma unroll
                for (int ni = 0; ni < 4; ni++)
                    mma_tf32(acc[mi][ni], af[mi], bf[ni]);
        }
        __syncthreads();
    }
#pragma unroll
    for (int mi = 0; mi < 2; mi++) {
        int r0r = m0 + wm + mi * 16 + grp;
        int r1r = r0r + 8;
#pragma unroll
        for (int ni = 0; ni < 4; ni++) {
            int c = n0 + wn + ni * 8 + t4 * 2;
            float b0 = bias ? bias[c] : 0.f;
            float b1 = bias ? bias[c + 1] : 0.f;
            if (geglu) {
                int co = c >> 1;
                if (r0r < M)
                    C[(size_t)r0r * Csm + co] = (acc[mi][ni][0] + b0) * gelu_f(acc[mi][ni][1] + b1);
                if (r1r < M)
                    C[(size_t)r1r * Csm + co] = (acc[mi][ni][2] + b0) * gelu_f(acc[mi][ni][3] + b1);
            } else {
                if (r0r < M) {
                    size_t o0 = (size_t)r0r * Csm + (size_t)c * Csn;
                    size_t o1 = o0 + Csn;
                    float v0 = acc[mi][ni][0] + b0;
                    float v1 = acc[mi][ni][1] + b1;
                    if (resid) { v0 += resid[o0]; v1 += resid[o1]; }
                    C[o0] = v0; C[o1] = v1;
                }
                if (r1r < M) {
                    size_t o0 = (size_t)r1r * Csm + (size_t)c * Csn;
                    size_t o1 = o0 + Csn;
                    float v0 = acc[mi][ni][2] + b0;
                    float v1 = acc[mi][ni][3] + b1;
                    if (resid) { v0 += resid[o0]; v1 += resid[o1]; }
                    C[o0] = v0; C[o1] = v1;
                }
            }
        }
    }
}

// ---------------- LayerNorm: warp per row, shuffle-only ----------------
__global__ __launch_bounds__(256) void ln_kernel(const float* __restrict__ in,
                                                 const float* __restrict__ w,
                                                 const float* __restrict__ b,
                                                 float* __restrict__ out) {
    int warp = threadIdx.x >> 5, lane = threadIdx.x & 31;
    int m = blockIdx.x * 8 + warp;
    const float* row = in + (size_t)m * DMODEL;
    float vals[10];
    float s = 0.f, ss = 0.f;
#pragma unroll
    for (int i = 0; i < 10; i++) {
        float v = row[lane + i * 32];
        vals[i] = v;
        s += v; ss += v * v;
    }
#pragma unroll
    for (int off = 16; off > 0; off >>= 1) {
        s += __shfl_xor_sync(0xffffffffu, s, off);
        ss += __shfl_xor_sync(0xffffffffu, ss, off);
    }
    float mu = s / (float)DMODEL;
    float var = ss / (float)DMODEL - mu * mu;
    float rs = rsqrtf(var + 1e-5f);
#pragma unroll
    for (int i = 0; i < 10; i++) {
        int c = lane + i * 32;
        out[(size_t)m * DMODEL + c] = (vals[i] - mu) * rs * w[c] + b[c];
    }
}

// ---------------- tensor-core flash attention (strided QKV) ----------------
#define ATTN_SMEM_BYTES (19456 * 4)
__global__ __launch_bounds__(256) void attn_tc(
    const float* __restrict__ Q, int ldq,
    const float* __restrict__ K, const float* __restrict__ V, int ldkv,
    float* __restrict__ O, int n_k) {
    extern __shared__ __align__(16) uint32_t dyn[];
    uint32_t* KrS = dyn;            // [2][64][44]
    uint32_t* VrS = dyn + 5632;     // [2][64][40]
    uint32_t* PsS = dyn + 10752;    // [128][68]
#define KR(st, r, c) KrS[(st) * 2816 + (r) * 44 + (c)]
#define VR(st, r, c) VrS[(st) * 2560 + (r) * 40 + (c)]
#define PS(r, c)     PsS[(r) * 68 + (c)]

    int h = blockIdx.y;
    int m0 = blockIdx.x * 128;
    int tid = threadIdx.x;
    int warp = tid >> 5, lane = tid & 31;
    int grp = lane >> 2, t4 = lane & 3;
    int wm = warp * 16;
    int row0 = m0 + wm + grp, row1 = row0 + 8;

    const float scale = 0.15811388300841897f;
    uint32_t qf[5][4];
#pragma unroll
    for (int kt = 0; kt < 5; kt++) {
        int c = kt * 8 + t4;
        qf[kt][0] = __float_as_uint(Q[(size_t)row0 * ldq + h * DH + c] * scale);
        qf[kt][1] = __float_as_uint(Q[(size_t)row1 * ldq + h * DH + c] * scale);
        qf[kt][2] = __float_as_uint(Q[(size_t)row0 * ldq + h * DH + c + 4] * scale);
        qf[kt][3] = __float_as_uint(Q[(size_t)row1 * ldq + h * DH + c + 4] * scale);
    }

    float o[5][4];
#pragma unroll
    for (int d = 0; d < 5; d++)
#pragma unroll
        for (int r = 0; r < 4; r++) o[d][r] = 0.f;
    float m_r0 = -1e30f, m_r1 = -1e30f, l_r0 = 0.f, l_r1 = 0.f;

    auto prefetch = [&](int st, int kt0) {
        for (int t = tid; t < 640; t += 256) {
            int r = t / 10, c4 = (t - r * 10) * 4;
            bool pred = (kt0 + r) < n_k;
            size_t g = (size_t)(pred ? (kt0 + r) : 0) * ldkv + h * DH + c4;
            cp16(smem_u32(&KR(st, r, c4)), K + g, pred);
            cp16(smem_u32(&VR(st, r, c4)), V + g, pred);
        }
    };

    int nT = (n_k + 63) >> 6;
    prefetch(0, 0);
    cp_commit();
    for (int it = 0; it < nT; it++) {
        if (it + 1 < nT) prefetch((it + 1) & 1, (it + 1) * 64);
        cp_commit();
        cp_wait1();
        __syncthreads();
        int st = it & 1;
        int kcount = min(64, n_k - it * 64);

        float s[8][4];
#pragma unroll
        for (int nt = 0; nt < 8; nt++)
#pragma unroll
            for (int r = 0; r < 4; r++) s[nt][r] = 0.f;
#pragma unroll
        for (int kt = 0; kt < 5; kt++) {
#pragma unroll
            for (int nt = 0; nt < 8; nt++) {
                uint32_t bf[2];
                bf[0] = KR(st, nt * 8 + grp, kt * 8 + t4);
                bf[1] = KR(st, nt * 8 + grp, kt * 8 + t4 + 4);
                mma_tf32(s[nt], qf[kt], bf);
            }
        }
        if (kcount < 64) {
#pragma unroll
            for (int nt = 0; nt < 8; nt++) {
                int c0 = nt * 8 + 2 * t4;
                if (c0 >= kcount)     { s[nt][0] = -1e30f; s[nt][2] = -1e30f; }
                if (c0 + 1 >= kcount) { s[nt][1] = -1e30f; s[nt][3] = -1e30f; }
            }
        }

        float mx0 = m_r0, mx1 = m_r1;
#pragma unroll
        for (int nt = 0; nt < 8; nt++) {
            mx0 = fmaxf(mx0, fmaxf(s[nt][0], s[nt][1]));
            mx1 = fmaxf(mx1, fmaxf(s[nt][2], s[nt][3]));
        }
        mx0 = fmaxf(mx0, __shfl_xor_sync(0xffffffffu, mx0, 1));
        mx0 = fmaxf(mx0, __shfl_xor_sync(0xffffffffu, mx0, 2));
        mx1 = fmaxf(mx1, __shfl_xor_sync(0xffffffffu, mx1, 1));
        mx1 = fmaxf(mx1, __shfl_xor_sync(0xffffffffu, mx1, 2));
        float f0 = __expf(m_r0 - mx0), f1 = __expf(m_r1 - mx1);
        float sum0 = 0.f, sum1 = 0.f;
#pragma unroll
        for (int nt = 0; nt < 8; nt++) {
            float p0 = __expf(s[nt][0] - mx0);
            float p1 = __expf(s[nt][1] - mx0);
            float p2 = __expf(s[nt][2] - mx1);
            float p3 = __expf(s[nt][3] - mx1);
            sum0 += p0 + p1; sum1 += p2 + p3;
            int c = nt * 8 + 2 * t4;
            PS(wm + grp, c)     = __float_as_uint(p0);
            PS(wm + grp, c + 1) = __float_as_uint(p1);
            PS(wm + grp + 8, c)     = __float_as_uint(p2);
            PS(wm + grp + 8, c + 1) = __float_as_uint(p3);
        }
        sum0 += __shfl_xor_sync(0xffffffffu, sum0, 1);
        sum0 += __shfl_xor_sync(0xffffffffu, sum0, 2);
        sum1 += __shfl_xor_sync(0xffffffffu, sum1, 1);
        sum1 += __shfl_xor_sync(0xffffffffu, sum1, 2);
        l_r0 = l_r0 * f0 + sum0; m_r0 = mx0;
        l_r1 = l_r1 * f1 + sum1; m_r1 = mx1;

#pragma unroll
        for (int d = 0; d < 5; d++) {
            o[d][0] *= f0; o[d][1] *= f0;
            o[d][2] *= f1; o[d][3] *= f1;
        }
        __syncwarp();

        uint32_t pa[8][4];
#pragma unroll
        for (int ks = 0; ks < 8; ks++) {
            pa[ks][0] = PS(wm + grp, ks * 8 + t4);
            pa[ks][1] = PS(wm + grp + 8, ks * 8 + t4);
            pa[ks][2] = PS(wm + grp, ks * 8 + t4 + 4);
            pa[ks][3] = PS(wm + grp + 8, ks * 8 + t4 + 4);
        }
#pragma unroll
        for (int d = 0; d < 5; d++) {
#pragma unroll
            for (int ks = 0; ks < 8; ks++) {
                uint32_t bf[2];
                bf[0] = VR(st, ks * 8 + t4, d * 8 + grp);
                bf[1] = VR(st, ks * 8 + t4 + 4, d * 8 + grp);
                mma_tf32(o[d], pa[ks], bf);
            }
        }
        __syncthreads();
    }

    float inv0 = 1.f / l_r0, inv1 = 1.f / l_r1;
#pragma unroll
    for (int d = 0; d < 5; d++) {
        int c = h * DH + d * 8 + 2 * t4;
        O[(size_t)row0 * DMODEL + c]     = o[d][0] * inv0;
        O[(size_t)row0 * DMODEL + c + 1] = o[d][1] * inv0;
        O[(size_t)row1 * DMODEL + c]     = o[d][2] * inv1;
        O[(size_t)row1 * DMODEL + c + 1] = o[d][3] * inv1;
    }
#undef KR
#undef VR
#undef PS
}

// ---------------- host launch ----------------
extern "C" void kernel_launch(void* const* d_in, const int* in_sizes, int n_in,
                              void* d_out, int out_size) {
    const float* x      = (const float*)d_in[0];
    const float* ctx    = (const float*)d_in[1];
    const float* gn_w   = (const float*)d_in[2];
    const float* gn_b   = (const float*)d_in[3];
    const float* pin_w  = (const float*)d_in[4];
    const float* pin_b  = (const float*)d_in[5];
    const float* ln1_w  = (const float*)d_in[6];
    const float* ln1_b  = (const float*)d_in[7];
    const float* q1     = (const float*)d_in[8];
    const float* k1     = (const float*)d_in[9];
    const float* v1     = (const float*)d_in[10];
    const float* o1_w   = (const float*)d_in[11];
    const float* o1_b   = (const float*)d_in[12];
    const float* ln2_w  = (const float*)d_in[13];
    const float* ln2_b  = (const float*)d_in[14];
    const float* q2     = (const float*)d_in[15];
    const float* k2     = (const float*)d_in[16];
    const float* v2     = (const float*)d_in[17];
    const float* o2_w   = (const float*)d_in[18];
    const float* o2_b   = (const float*)d_in[19];
    const float* ln3_w  = (const float*)d_in[20];
    const float* ln3_b  = (const float*)d_in[21];
    const float* ff1_w  = (const float*)d_in[22];
    const float* ff1_b  = (const float*)d_in[23];
    const float* ff2_w  = (const float*)d_in[24];
    const float* ff2_b  = (const float*)d_in[25];
    const float* pout_w = (const float*)d_in[26];
    const float* pout_b = (const float*)d_in[27];
    float* out = (float*)d_out;

    float *Wp, *Wq, *bp, *xt, *h, *ln, *qb, *qkv, *kv2, *ao, *fa;
    float *wqkv, *wkv2, *wff1, *bff1;
    cudaGetSymbolAddress((void**)&Wp, g_Wp);
    cudaGetSymbolAddress((void**)&Wq, g_Wq);
    cudaGetSymbolAddress((void**)&bp, g_bp);
    cudaGetSymbolAddress((void**)&xt, g_xt);
    cudaGetSymbolAddress((void**)&h,  g_h);
    cudaGetSymbolAddress((void**)&ln, g_ln);
    cudaGetSymbolAddress((void**)&qb, g_qb);
    cudaGetSymbolAddress((void**)&qkv, g_qkv);
    cudaGetSymbolAddress((void**)&kv2, g_kv2);
    cudaGetSymbolAddress((void**)&ao, g_ao);
    cudaGetSymbolAddress((void**)&fa, g_fa);
    cudaGetSymbolAddress((void**)&wqkv, g_wqkv);
    cudaGetSymbolAddress((void**)&wkv2, g_wkv2);
    cudaGetSymbolAddress((void**)&wff1, g_wff1);
    cudaGetSymbolAddress((void**)&bff1, g_bff1);

    static bool attr_set = false;
    if (!attr_set) {
        cudaFuncSetAttribute(attn_tc, cudaFuncAttributeMaxDynamicSharedMemorySize,
                             ATTN_SMEM_BYTES);
        attr_set = true;
    }

    // prep
    gn_stats_kernel<<<32, 256>>>(x, gn_w, gn_b);
    fold_pin_kernel<<<DMODEL, 64>>>(pin_w, pin_b);
    transpose_kernel<<<dim3(128, 10), dim3(32, 8)>>>(x, xt, DMODEL, NTOK);
    transpose_kernel<<<dim3(10, 10), dim3(32, 8)>>>(pout_w, Wq, DMODEL, DMODEL);
    concat3_kernel<<<(DMODEL * DMODEL + 255) / 256, 256>>>(q1, k1, v1, wqkv, DMODEL, DMODEL);
    concat2_kernel<<<(CTXD * DMODEL + 255) / 256, 256>>>(k2, v2, wkv2, CTXD, DMODEL);
    ffperm_kernel<<<(DMODEL * FFI + 255) / 256, 256>>>(ff1_w, ff1_b, wff1, bff1);

    // pin projection
    gemm_tc<<<dim3(32, 5), 256>>>(xt, Wp, h, bp, nullptr,
        NTOK, DMODEL, DMODEL, DMODEL, DMODEL, DMODEL, 1, 0);

    // self-attention block
    ln_kernel<<<NTOK / 8, 256>>>(h, ln1_w, ln1_b, ln);
    gemm_tc<<<dim3(32, 15), 256>>>(ln, wqkv, qkv, nullptr, nullptr,
        NTOK, 3 * DMODEL, DMODEL, DMODEL, 3 * DMODEL, 3 * DMODEL, 1, 0);
    attn_tc<<<dim3(NTOK / 128, HEADS), 256, ATTN_SMEM_BYTES>>>(
        qkv, 3 * DMODEL, qkv + DMODEL, qkv + 2 * DMODEL, 3 * DMODEL, ao, NTOK);
    gemm_tc<<<dim3(32, 5), 256>>>(ao, o1_w, h, o1_b, h,
        NTOK, DMODEL, DMODEL, DMODEL, DMODEL, DMODEL, 1, 0);

    // cross-attention block
    ln_kernel<<<NTOK / 8, 256>>>(h, ln2_w, ln2_b, ln);
    gemm_tc<<<dim3(32, 5), 256>>>(ln, q2, qb, nullptr, nullptr,
        NTOK, DMODEL, DMODEL, DMODEL, DMODEL, DMODEL, 1, 0);
    gemm_tc<<<dim3(1, 10), 256>>>(ctx, wkv2, kv2, nullptr, nullptr,
        CTXN, 2 * DMODEL, CTXD, CTXD, 2 * DMODEL, 2 * DMODEL, 1, 0);
    attn_tc<<<dim3(NTOK / 128, HEADS), 256, ATTN_SMEM_BYTES>>>(
        qb, DMODEL, kv2, kv2 + DMODEL, 2 * DMODEL, ao, CTXN);
    gemm_tc<<<dim3(32, 5), 256>>>(ao, o2_w, h, o2_b, h,
        NTOK, DMODEL, DMODEL, DMODEL, DMODEL, DMODEL, 1, 0);

    // GEGLU FF block (gelu fused into ff1 epilogue via interleaved columns)
    ln_kernel<<<NTOK / 8, 256>>>(h, ln3_w, ln3_b, ln);
    gemm_tc<<<dim3(32, 40), 256>>>(ln, wff1, fa, bff1, nullptr,
        NTOK, 2 * FFI, DMODEL, DMODEL, 2 * FFI, FFI, 1, 1);
    gemm_tc<<<dim3(32, 5), 256>>>(fa, ff2_w, h, ff2_b, h,
        NTOK, DMODEL, FFI, FFI, DMODEL, DMODEL, 1, 0);

    // output projection (transposed store) + input residual
    gemm_tc<<<dim3(32, 5), 256>>>(h, Wq, out, pout_b, x,
        NTOK, DMODEL, DMODEL, DMODEL, DMODEL, 1, NTOK, 0);
}